// round 10
// baseline (speedup 1.0000x reference)
#include <cuda_runtime.h>
#include <cuda_bf16.h>
#include <cstdint>
#include <math.h>

// Problem constants
#define BATCH 2
#define SEQ   2048
#define CMODEL 1024
#define NHEAD 16
#define HDIM  64
#define MROWS (BATCH * SEQ)   // 4096

// ---------------------------------------------------------------------------
// Scratch
// ---------------------------------------------------------------------------
__device__ float g_q[MROWS * CMODEL];
__device__ float g_k[MROWS * CMODEL];
__device__ float g_v[MROWS * CMODEL];
__device__ float g_attn[MROWS * CMODEL];

// ---------------------------------------------------------------------------
// Helpers
// ---------------------------------------------------------------------------
__device__ __forceinline__ uint32_t smem_u32(const void* p) {
    uint32_t a;
    asm("{ .reg .u64 t; cvta.to.shared.u64 t, %1; cvt.u32.u64 %0, t; }" : "=r"(a) : "l"(p));
    return a;
}
__device__ __forceinline__ void cp_async16(uint32_t s, const void* g) {
    asm volatile("cp.async.ca.shared.global [%0], [%1], 16;" :: "r"(s), "l"(g));
}
#define CP_COMMIT()  asm volatile("cp.async.commit_group;" ::: "memory")
#define CP_WAIT(N)   asm volatile("cp.async.wait_group %0;" :: "n"(N) : "memory")

__device__ __forceinline__ uint32_t f2tf32(float f) {
    uint32_t u;
    asm("cvt.rna.tf32.f32 %0, %1;" : "=r"(u) : "f"(f));
    return u;
}
__device__ __forceinline__ void mma_tf32(float (&d)[4], const uint32_t (&a)[4],
                                         const uint32_t (&b)[2]) {
    asm volatile(
        "mma.sync.aligned.m16n8k8.row.col.f32.tf32.tf32.f32 "
        "{%0,%1,%2,%3}, {%4,%5,%6,%7}, {%8,%9}, {%0,%1,%2,%3};"
        : "+f"(d[0]), "+f"(d[1]), "+f"(d[2]), "+f"(d[3])
        : "r"(a[0]), "r"(a[1]), "r"(a[2]), "r"(a[3]), "r"(b[0]), "r"(b[1]));
}

// ---------------------------------------------------------------------------
// TF32 mma.sync GEMM body: C[m][n] = sum_k A[m][k] * W[n][k]
// CTA tile 256x128, BK=32, 512 threads = 16 warps in 4(M) x 4(N);
// warp tile 64x32. Optional fused RoPE; optional tf32-rounding of outputs.
// ---------------------------------------------------------------------------
#define BK 32
#define KST 36                       // padded row stride (floats)
#define ATF (256 * KST)
#define WTF (128 * KST)
#define STAGEF (ATF + WTF)
#define G2SMEM_FLOATS (2 * STAGEF)   // 110592 bytes

__device__ __forceinline__ void gemm_body(const float* __restrict__ A,
                                          const float* __restrict__ W,
                                          float* __restrict__ C,
                                          const float* __restrict__ freqs,
                                          int m0, int n0, bool rope, bool roundout,
                                          float* smem) {
    const int K = CMODEL, N = CMODEL;
    float* As[2] = { smem,          smem + STAGEF };
    float* Ws[2] = { smem + ATF,    smem + STAGEF + ATF };

    const int tid  = threadIdx.x;
    const int lane = tid & 31;
    const int wid  = tid >> 5;       // 0..15
    const int g    = lane >> 2;
    const int tg   = lane & 3;
    const int wm   = (wid & 3) * 64;
    const int wn   = (wid >> 2) * 32;

    float acc[4][4][4];
#pragma unroll
    for (int mt = 0; mt < 4; mt++)
#pragma unroll
        for (int nt = 0; nt < 4; nt++)
#pragma unroll
            for (int r = 0; r < 4; r++) acc[mt][nt][r] = 0.0f;

    const int ntiles = K / BK;

    auto load_tile = [&](int kt, int stg) {
        const int ko = kt * BK;
#pragma unroll
        for (int i = 0; i < 4; i++) {
            const int f = tid + 512 * i;       // 0..2047
            const int row = f >> 3;
            const int c4 = (f & 7) * 4;
            cp_async16(smem_u32(&As[stg][row * KST + c4]),
                       &A[(size_t)(m0 + row) * K + ko + c4]);
        }
#pragma unroll
        for (int i = 0; i < 2; i++) {
            const int f = tid + 512 * i;       // 0..1023
            const int row = f >> 3;
            const int c4 = (f & 7) * 4;
            cp_async16(smem_u32(&Ws[stg][row * KST + c4]),
                       &W[(size_t)(n0 + row) * K + ko + c4]);
        }
    };

    load_tile(0, 0);
    CP_COMMIT();

    for (int kt = 0; kt < ntiles; kt++) {
        const int buf = kt & 1;
        if (kt + 1 < ntiles) {
            load_tile(kt + 1, (kt + 1) & 1);
            CP_COMMIT();
            CP_WAIT(1);
        } else {
            CP_WAIT(0);
        }
        __syncthreads();

        const float* at = As[buf];
        const float* wt = Ws[buf];
#pragma unroll
        for (int ks = 0; ks < 4; ks++) {
            const int kc = ks * 8 + tg;
            uint32_t a[4][4];
#pragma unroll
            for (int mt = 0; mt < 4; mt++) {
                const int r0 = (wm + mt * 16 + g) * KST;
                a[mt][0] = f2tf32(at[r0 + kc]);
                a[mt][1] = f2tf32(at[r0 + 8 * KST + kc]);
                a[mt][2] = f2tf32(at[r0 + kc + 4]);
                a[mt][3] = f2tf32(at[r0 + 8 * KST + kc + 4]);
            }
            uint32_t b[4][2];
#pragma unroll
            for (int nt = 0; nt < 4; nt++) {
                const int r0 = (wn + nt * 8 + g) * KST;
                b[nt][0] = f2tf32(wt[r0 + kc]);
                b[nt][1] = f2tf32(wt[r0 + kc + 4]);
            }
#pragma unroll
            for (int mt = 0; mt < 4; mt++)
#pragma unroll
                for (int nt = 0; nt < 4; nt++)
                    mma_tf32(acc[mt][nt], a[mt], b[nt]);
        }
        __syncthreads();
    }

    // epilogue: optional fused RoPE, optional tf32 rounding of stored values
#pragma unroll
    for (int mt = 0; mt < 4; mt++) {
        const int row = m0 + wm + mt * 16 + g;
        const int t0 = row & (SEQ - 1);
        const int t1 = (row + 8) & (SEQ - 1);
#pragma unroll
        for (int nt = 0; nt < 4; nt++) {
            const int col = n0 + wn + nt * 8 + 2 * tg;
            float2 v0 = make_float2(acc[mt][nt][0], acc[mt][nt][1]);
            float2 v1 = make_float2(acc[mt][nt][2], acc[mt][nt][3]);
            if (rope) {
                const int fo = (col & 62);
                float cc0 = freqs[t0 * HDIM + fo], ss0 = freqs[t0 * HDIM + fo + 1];
                float cc1 = freqs[t1 * HDIM + fo], ss1 = freqs[t1 * HDIM + fo + 1];
                v0 = make_float2(v0.x * cc0 - v0.y * ss0, v0.x * ss0 + v0.y * cc0);
                v1 = make_float2(v1.x * cc1 - v1.y * ss1, v1.x * ss1 + v1.y * cc1);
            }
            if (roundout) {
                v0.x = __uint_as_float(f2tf32(v0.x));
                v0.y = __uint_as_float(f2tf32(v0.y));
                v1.x = __uint_as_float(f2tf32(v1.x));
                v1.y = __uint_as_float(f2tf32(v1.y));
            }
            *reinterpret_cast<float2*>(&C[(size_t)row * N + col]) = v0;
            *reinterpret_cast<float2*>(&C[(size_t)(row + 8) * N + col]) = v1;
        }
    }
}

// Fused QKV + RoPE, outputs tf32-rounded for cvt-free attention
__global__ __launch_bounds__(512, 1) void gemm_qkv(const float* __restrict__ x,
                                                   const float* __restrict__ Wq,
                                                   const float* __restrict__ Wk,
                                                   const float* __restrict__ Wv,
                                                   float* __restrict__ q,
                                                   float* __restrict__ k,
                                                   float* __restrict__ v,
                                                   const float* __restrict__ freqs) {
    extern __shared__ float smem[];
    const int wsel = blockIdx.x >> 3;
    const int n0 = (blockIdx.x & 7) * 128;
    const int m0 = blockIdx.y * 256;
    const float* W = (wsel == 0) ? Wq : (wsel == 1) ? Wk : Wv;
    float* C = (wsel == 0) ? q : (wsel == 1) ? k : v;
    gemm_body(x, W, C, freqs, m0, n0, wsel < 2, true, smem);
}

__global__ __launch_bounds__(512, 1) void gemm_proj(const float* __restrict__ A,
                                                    const float* __restrict__ W,
                                                    float* __restrict__ C) {
    extern __shared__ float smem[];
    gemm_body(A, W, C, nullptr, blockIdx.y * 256, blockIdx.x * 128, false, false, smem);
}

// ---------------------------------------------------------------------------
// Tensor-core flash-attention, cvt-free operands, 2 CTAs/SM for latency
// hiding (smem 104.4KB x2 = 208.9KB fits the 227KB carveout).
// ---------------------------------------------------------------------------
#define APAD 68
#define ATILE (64 * APAD)
#define ASMEM_FLOATS (4 * ATILE + 128 * APAD)

__global__ __launch_bounds__(256, 2) void flash_attn_mma(const float* __restrict__ Q,
                                                         const float* __restrict__ K,
                                                         const float* __restrict__ V,
                                                         float* __restrict__ O) {
    extern __shared__ float sm[];
    float* Ksm[2] = { sm,             sm + 2 * ATILE };
    float* Vsm[2] = { sm + ATILE,     sm + 3 * ATILE };
    float* Ps = sm + 4 * ATILE;

    const int tid  = threadIdx.x;
    const int lane = tid & 31;
    const int wid  = tid >> 5;
    const int g    = lane >> 2;
    const int tg   = lane & 3;

    const int qb = (int)gridDim.x - 1 - (int)blockIdx.x;
    const int h  = blockIdx.y;
    const int b  = blockIdx.z;
    const int q0 = qb * 128;
    const int wrow = wid * 16;
    const int r0g = q0 + wrow + g;
    const int r1g = r0g + 8;

    const float scale = 0.125f;   // pow2: tf32-exact scaling
    uint32_t qf[8][4];
    {
        const float* q0p = Q + (((size_t)b * SEQ + r0g) * NHEAD + h) * HDIM;
        const float* q1p = Q + (((size_t)b * SEQ + r1g) * NHEAD + h) * HDIM;
#pragma unroll
        for (int ks = 0; ks < 8; ks++) {
            const int kc = ks * 8 + tg;
            qf[ks][0] = __float_as_uint(q0p[kc] * scale);
            qf[ks][1] = __float_as_uint(q1p[kc] * scale);
            qf[ks][2] = __float_as_uint(q0p[kc + 4] * scale);
            qf[ks][3] = __float_as_uint(q1p[kc + 4] * scale);
        }
    }

    float of[8][4];
#pragma unroll
    for (int nt = 0; nt < 8; nt++)
#pragma unroll
        for (int r = 0; r < 4; r++) of[nt][r] = 0.0f;
    float mrow[2] = { -1e30f, -1e30f };
    float lrow[2] = { 0.0f, 0.0f };

    const int ntiles = (q0 + 128) / 64;

    const uint32_t ks0 = smem_u32(Ksm[0]);
    const uint32_t vs0 = smem_u32(Vsm[0]);
    const uint32_t stageB = 2 * ATILE * 4;

    auto prefetch = [&](int t, int s) {
        const int kt = t * 64;
#pragma unroll
        for (int i = 0; i < 4; i++) {
            const int f = tid + 256 * i;
            const int row = f >> 4;
            const int c4 = (f & 15) * 4;
            const size_t gsrc = (((size_t)b * SEQ + kt + row) * NHEAD + h) * HDIM + c4;
            const uint32_t soff = s * stageB + (row * APAD + c4) * 4;
            cp_async16(ks0 + soff, &K[gsrc]);
            cp_async16(vs0 + soff, &V[gsrc]);
        }
    };

    prefetch(0, 0);
    CP_COMMIT();

    for (int t = 0; t < ntiles; t++) {
        const int kt = t * 64;
        if (t + 1 < ntiles) {
            prefetch(t + 1, (t + 1) & 1);
            CP_COMMIT();
            CP_WAIT(1);
        } else {
            CP_WAIT(0);
        }
        __syncthreads();

        const bool skip = kt > q0 + wrow + 15;
        if (!skip) {
            const float* kb = Ksm[t & 1];
            const float* vb = Vsm[t & 1];

            float sacc[8][4];
#pragma unroll
            for (int nt = 0; nt < 8; nt++)
#pragma unroll
                for (int r = 0; r < 4; r++) sacc[nt][r] = 0.0f;

#pragma unroll
            for (int ks = 0; ks < 8; ks++) {
                const int kc = ks * 8 + tg;
#pragma unroll
                for (int nt = 0; nt < 8; nt++) {
                    uint32_t bf[2];
                    bf[0] = __float_as_uint(kb[(nt * 8 + g) * APAD + kc]);
                    bf[1] = __float_as_uint(kb[(nt * 8 + g) * APAD + kc + 4]);
                    mma_tf32(sacc[nt], qf[ks], bf);
                }
            }

            if (kt + 63 > q0 + wrow) {
#pragma unroll
                for (int nt = 0; nt < 8; nt++) {
                    const int c = kt + nt * 8 + 2 * tg;
                    if (c > r0g)     sacc[nt][0] = -1e30f;
                    if (c + 1 > r0g) sacc[nt][1] = -1e30f;
                    if (c > r1g)     sacc[nt][2] = -1e30f;
                    if (c + 1 > r1g) sacc[nt][3] = -1e30f;
                }
            }

            float rmax0 = -1e30f, rmax1 = -1e30f;
#pragma unroll
            for (int nt = 0; nt < 8; nt++) {
                rmax0 = fmaxf(rmax0, fmaxf(sacc[nt][0], sacc[nt][1]));
                rmax1 = fmaxf(rmax1, fmaxf(sacc[nt][2], sacc[nt][3]));
            }
            rmax0 = fmaxf(rmax0, __shfl_xor_sync(0xffffffff, rmax0, 1));
            rmax0 = fmaxf(rmax0, __shfl_xor_sync(0xffffffff, rmax0, 2));
            rmax1 = fmaxf(rmax1, __shfl_xor_sync(0xffffffff, rmax1, 1));
            rmax1 = fmaxf(rmax1, __shfl_xor_sync(0xffffffff, rmax1, 2));

            const float mn0 = fmaxf(mrow[0], rmax0);
            const float mn1 = fmaxf(mrow[1], rmax1);
            const float corr0 = __expf(mrow[0] - mn0);
            const float corr1 = __expf(mrow[1] - mn1);
            mrow[0] = mn0; mrow[1] = mn1;

            float rs0 = 0.0f, rs1 = 0.0f;
            float* p0row = &Ps[(wrow + g) * APAD + 2 * tg];
            float* p1row = &Ps[(wrow + g + 8) * APAD + 2 * tg];
#pragma unroll
            for (int nt = 0; nt < 8; nt++) {
                const float e0 = __expf(sacc[nt][0] - mn0);
                const float e1 = __expf(sacc[nt][1] - mn0);
                const float e2 = __expf(sacc[nt][2] - mn1);
                const float e3 = __expf(sacc[nt][3] - mn1);
                rs0 += e0 + e1;
                rs1 += e2 + e3;
                *reinterpret_cast<float2*>(p0row + nt * 8) =
                    make_float2(__uint_as_float(f2tf32(e0)), __uint_as_float(f2tf32(e1)));
                *reinterpret_cast<float2*>(p1row + nt * 8) =
                    make_float2(__uint_as_float(f2tf32(e2)), __uint_as_float(f2tf32(e3)));
            }
            rs0 += __shfl_xor_sync(0xffffffff, rs0, 1);
            rs0 += __shfl_xor_sync(0xffffffff, rs0, 2);
            rs1 += __shfl_xor_sync(0xffffffff, rs1, 1);
            rs1 += __shfl_xor_sync(0xffffffff, rs1, 2);
            lrow[0] = lrow[0] * corr0 + rs0;
            lrow[1] = lrow[1] * corr1 + rs1;

#pragma unroll
            for (int nt = 0; nt < 8; nt++) {
                of[nt][0] *= corr0; of[nt][1] *= corr0;
                of[nt][2] *= corr1; of[nt][3] *= corr1;
            }
            __syncwarp();

#pragma unroll
            for (int ks = 0; ks < 8; ks++) {
                const int kc = ks * 8 + tg;
                uint32_t a[4];
                a[0] = __float_as_uint(Ps[(wrow + g) * APAD + kc]);
                a[1] = __float_as_uint(Ps[(wrow + g + 8) * APAD + kc]);
                a[2] = __float_as_uint(Ps[(wrow + g) * APAD + kc + 4]);
                a[3] = __float_as_uint(Ps[(wrow + g + 8) * APAD + kc + 4]);
#pragma unroll
                for (int nt = 0; nt < 8; nt++) {
                    uint32_t bf[2];
                    bf[0] = __float_as_uint(vb[kc * APAD + nt * 8 + g]);
                    bf[1] = __float_as_uint(vb[(kc + 4) * APAD + nt * 8 + g]);
                    mma_tf32(of[nt], a, bf);
                }
            }
        }
        __syncthreads();
    }

    const float inv0 = 1.0f / lrow[0];
    const float inv1 = 1.0f / lrow[1];
    float* o0 = O + (((size_t)b * SEQ + r0g) * NHEAD + h) * HDIM;
    float* o1 = O + (((size_t)b * SEQ + r1g) * NHEAD + h) * HDIM;
#pragma unroll
    for (int nt = 0; nt < 8; nt++) {
        const int col = nt * 8 + 2 * tg;
        *reinterpret_cast<float2*>(o0 + col) = make_float2(of[nt][0] * inv0, of[nt][1] * inv0);
        *reinterpret_cast<float2*>(o1 + col) = make_float2(of[nt][2] * inv1, of[nt][3] * inv1);
    }
}

// ---------------------------------------------------------------------------
// kernel_launch
// ---------------------------------------------------------------------------
extern "C" void kernel_launch(void* const* d_in, const int* in_sizes, int n_in,
                              void* d_out, int out_size) {
    const float* x     = (const float*)d_in[0];
    const float* freqs = (const float*)d_in[1];
    const float* Wq    = (const float*)d_in[2];
    const float* Wk    = (const float*)d_in[3];
    const float* Wv    = (const float*)d_in[4];
    const float* Wo    = (const float*)d_in[5];
    float* out = (float*)d_out;

    float *q = nullptr, *k = nullptr, *v = nullptr, *attn = nullptr;
    cudaGetSymbolAddress((void**)&q,    g_q);
    cudaGetSymbolAddress((void**)&k,    g_k);
    cudaGetSymbolAddress((void**)&v,    g_v);
    cudaGetSymbolAddress((void**)&attn, g_attn);

    const int gsmem = G2SMEM_FLOATS * sizeof(float);   // 110592
    cudaFuncSetAttribute(gemm_qkv,  cudaFuncAttributeMaxDynamicSharedMemorySize, gsmem);
    cudaFuncSetAttribute(gemm_proj, cudaFuncAttributeMaxDynamicSharedMemorySize, gsmem);
    const int asmem = ASMEM_FLOATS * sizeof(float);    // 104448
    cudaFuncSetAttribute(flash_attn_mma, cudaFuncAttributeMaxDynamicSharedMemorySize, asmem);

    gemm_qkv<<<dim3(24, MROWS / 256), 512, gsmem>>>(x, Wq, Wk, Wv, q, k, v, freqs);

    {
        dim3 agrid(SEQ / 128, NHEAD, BATCH);
        flash_attn_mma<<<agrid, 256, asmem>>>(q, k, v, attn);
    }

    gemm_proj<<<dim3(CMODEL / 128, MROWS / 256), 512, gsmem>>>(attn, Wo, out);
}

// round 11
// speedup vs baseline: 1.2246x; 1.2246x over previous
#include <cuda_runtime.h>
#include <cuda_fp16.h>
#include <cuda_bf16.h>
#include <cstdint>
#include <math.h>

// Problem constants
#define BATCH 2
#define SEQ   2048
#define CMODEL 1024
#define NHEAD 16
#define HDIM  64
#define MROWS (BATCH * SEQ)   // 4096

// ---------------------------------------------------------------------------
// Scratch
// ---------------------------------------------------------------------------
__device__ float  g_q[MROWS * CMODEL];
__device__ float  g_k[MROWS * CMODEL];
__device__ float  g_v[MROWS * CMODEL];
__device__ __half g_attnh[MROWS * CMODEL];
__device__ __half g_xh[MROWS * CMODEL];
__device__ __half g_wh[4 * CMODEL * CMODEL];   // Wq,Wk,Wv,Wo in half

// ---------------------------------------------------------------------------
// Helpers
// ---------------------------------------------------------------------------
__device__ __forceinline__ uint32_t smem_u32(const void* p) {
    uint32_t a;
    asm("{ .reg .u64 t; cvta.to.shared.u64 t, %1; cvt.u32.u64 %0, t; }" : "=r"(a) : "l"(p));
    return a;
}
__device__ __forceinline__ void cp_async16(uint32_t s, const void* g) {
    asm volatile("cp.async.ca.shared.global [%0], [%1], 16;" :: "r"(s), "l"(g));
}
#define CP_COMMIT()  asm volatile("cp.async.commit_group;" ::: "memory")
#define CP_WAIT(N)   asm volatile("cp.async.wait_group %0;" :: "n"(N) : "memory")

__device__ __forceinline__ uint32_t f2tf32(float f) {
    uint32_t u;
    asm("cvt.rna.tf32.f32 %0, %1;" : "=r"(u) : "f"(f));
    return u;
}
__device__ __forceinline__ void mma_tf32(float (&d)[4], const uint32_t (&a)[4],
                                         const uint32_t (&b)[2]) {
    asm volatile(
        "mma.sync.aligned.m16n8k8.row.col.f32.tf32.tf32.f32 "
        "{%0,%1,%2,%3}, {%4,%5,%6,%7}, {%8,%9}, {%0,%1,%2,%3};"
        : "+f"(d[0]), "+f"(d[1]), "+f"(d[2]), "+f"(d[3])
        : "r"(a[0]), "r"(a[1]), "r"(a[2]), "r"(a[3]), "r"(b[0]), "r"(b[1]));
}
__device__ __forceinline__ void mma_f16(float (&d)[4], const uint32_t (&a)[4],
                                        const uint32_t (&b)[2]) {
    asm volatile(
        "mma.sync.aligned.m16n8k16.row.col.f32.f16.f16.f32 "
        "{%0,%1,%2,%3}, {%4,%5,%6,%7}, {%8,%9}, {%0,%1,%2,%3};"
        : "+f"(d[0]), "+f"(d[1]), "+f"(d[2]), "+f"(d[3])
        : "r"(a[0]), "r"(a[1]), "r"(a[2]), "r"(a[3]), "r"(b[0]), "r"(b[1]));
}

// ---------------------------------------------------------------------------
// Prepass: fp32 -> fp16, row-major, 8 elements per thread
// ---------------------------------------------------------------------------
__global__ void to_half(const float* __restrict__ src, __half* __restrict__ dst,
                        int n) {
    int i = (blockIdx.x * 256 + threadIdx.x) * 8;
    if (i >= n) return;
    float4 v0 = *reinterpret_cast<const float4*>(src + i);
    float4 v1 = *reinterpret_cast<const float4*>(src + i + 4);
    __half2 h[4];
    h[0] = __floats2half2_rn(v0.x, v0.y);
    h[1] = __floats2half2_rn(v0.z, v0.w);
    h[2] = __floats2half2_rn(v1.x, v1.y);
    h[3] = __floats2half2_rn(v1.z, v1.w);
    *reinterpret_cast<uint2*>(dst + i)     = *reinterpret_cast<uint2*>(&h[0]);
    *reinterpret_cast<uint2*>(dst + i + 4) = *reinterpret_cast<uint2*>(&h[2]);
}

// ---------------------------------------------------------------------------
// FP16 mma.sync GEMM body: C[m][n] = sum_k A[m][k] * W[n][k], fp32 accum/out.
// CTA tile 256x128, BK=32 (2 k16-steps), 512 threads = 16 warps 4(M)x4(N);
// warp tile 64x32. Per tile per warp: 48 LDS.32 + 32 MMA.
// ---------------------------------------------------------------------------
#define BK 32
#define KSTH 40                       // padded row stride (halves)
#define ATH (256 * KSTH)              // halves
#define WTH (128 * KSTH)
#define STAGEH (ATH + WTH)
#define GH_SMEM_BYTES (2 * STAGEH * 2)   // 61440

__device__ __forceinline__ void gemm_body_h(const __half* __restrict__ A,
                                            const __half* __restrict__ W,
                                            float* __restrict__ C,
                                            const float* __restrict__ freqs,
                                            int m0, int n0, bool rope, bool roundout,
                                            __half* smem) {
    const int K = CMODEL, N = CMODEL;
    __half* As[2] = { smem,         smem + STAGEH };
    __half* Ws[2] = { smem + ATH,   smem + STAGEH + ATH };

    const int tid  = threadIdx.x;
    const int lane = tid & 31;
    const int wid  = tid >> 5;       // 0..15
    const int g    = lane >> 2;
    const int tg   = lane & 3;
    const int wm   = (wid & 3) * 64;
    const int wn   = (wid >> 2) * 32;

    float acc[4][4][4];
#pragma unroll
    for (int mt = 0; mt < 4; mt++)
#pragma unroll
        for (int nt = 0; nt < 4; nt++)
#pragma unroll
            for (int r = 0; r < 4; r++) acc[mt][nt][r] = 0.0f;

    const int ntiles = K / BK;

    // loaders: A tile 1024 16B-chunks (2/thread), W tile 512 (1/thread)
    auto load_tile = [&](int kt, int stg) {
        const int ko = kt * BK;     // half offset
#pragma unroll
        for (int i = 0; i < 2; i++) {
            const int f = tid + 512 * i;       // 0..1023
            const int row = f >> 2;
            const int c8 = (f & 3) * 8;
            cp_async16(smem_u32(&As[stg][row * KSTH + c8]),
                       &A[(size_t)(m0 + row) * K + ko + c8]);
        }
        {
            const int row = tid >> 2;          // 0..127
            const int c8 = (tid & 3) * 8;
            cp_async16(smem_u32(&Ws[stg][row * KSTH + c8]),
                       &W[(size_t)(n0 + row) * K + ko + c8]);
        }
    };

    load_tile(0, 0);
    CP_COMMIT();

    for (int kt = 0; kt < ntiles; kt++) {
        const int buf = kt & 1;
        if (kt + 1 < ntiles) {
            load_tile(kt + 1, (kt + 1) & 1);
            CP_COMMIT();
            CP_WAIT(1);
        } else {
            CP_WAIT(0);
        }
        __syncthreads();

        const __half* at = As[buf];
        const __half* wt = Ws[buf];
#pragma unroll
        for (int ks = 0; ks < 2; ks++) {
            const int kc = ks * 16 + 2 * tg;   // half index
            uint32_t a[4][4];
#pragma unroll
            for (int mt = 0; mt < 4; mt++) {
                const int r0 = (wm + mt * 16 + g) * KSTH;
                a[mt][0] = *reinterpret_cast<const uint32_t*>(at + r0 + kc);
                a[mt][1] = *reinterpret_cast<const uint32_t*>(at + r0 + 8 * KSTH + kc);
                a[mt][2] = *reinterpret_cast<const uint32_t*>(at + r0 + kc + 8);
                a[mt][3] = *reinterpret_cast<const uint32_t*>(at + r0 + 8 * KSTH + kc + 8);
            }
            uint32_t b[4][2];
#pragma unroll
            for (int nt = 0; nt < 4; nt++) {
                const int r0 = (wn + nt * 8 + g) * KSTH;
                b[nt][0] = *reinterpret_cast<const uint32_t*>(wt + r0 + kc);
                b[nt][1] = *reinterpret_cast<const uint32_t*>(wt + r0 + kc + 8);
            }
#pragma unroll
            for (int mt = 0; mt < 4; mt++)
#pragma unroll
                for (int nt = 0; nt < 4; nt++)
                    mma_f16(acc[mt][nt], a[mt], b[nt]);
        }
        __syncthreads();
    }

    // epilogue: optional fused RoPE, optional tf32 rounding of stored values
#pragma unroll
    for (int mt = 0; mt < 4; mt++) {
        const int row = m0 + wm + mt * 16 + g;
        const int t0 = row & (SEQ - 1);
        const int t1 = (row + 8) & (SEQ - 1);
#pragma unroll
        for (int nt = 0; nt < 4; nt++) {
            const int col = n0 + wn + nt * 8 + 2 * tg;
            float2 v0 = make_float2(acc[mt][nt][0], acc[mt][nt][1]);
            float2 v1 = make_float2(acc[mt][nt][2], acc[mt][nt][3]);
            if (rope) {
                const int fo = (col & 62);
                float cc0 = freqs[t0 * HDIM + fo], ss0 = freqs[t0 * HDIM + fo + 1];
                float cc1 = freqs[t1 * HDIM + fo], ss1 = freqs[t1 * HDIM + fo + 1];
                v0 = make_float2(v0.x * cc0 - v0.y * ss0, v0.x * ss0 + v0.y * cc0);
                v1 = make_float2(v1.x * cc1 - v1.y * ss1, v1.x * ss1 + v1.y * cc1);
            }
            if (roundout) {
                v0.x = __uint_as_float(f2tf32(v0.x));
                v0.y = __uint_as_float(f2tf32(v0.y));
                v1.x = __uint_as_float(f2tf32(v1.x));
                v1.y = __uint_as_float(f2tf32(v1.y));
            }
            *reinterpret_cast<float2*>(&C[(size_t)row * N + col]) = v0;
            *reinterpret_cast<float2*>(&C[(size_t)(row + 8) * N + col]) = v1;
        }
    }
}

// Fused QKV + RoPE; outputs fp32 tf32-rounded for cvt-free attention
__global__ __launch_bounds__(512, 1) void gemm_qkv(const __half* __restrict__ xh,
                                                   const __half* __restrict__ wh,
                                                   float* __restrict__ q,
                                                   float* __restrict__ k,
                                                   float* __restrict__ v,
                                                   const float* __restrict__ freqs) {
    extern __shared__ __half smemh[];
    const int wsel = blockIdx.x >> 3;
    const int n0 = (blockIdx.x & 7) * 128;
    const int m0 = blockIdx.y * 256;
    const __half* W = wh + (size_t)wsel * CMODEL * CMODEL;
    float* C = (wsel == 0) ? q : (wsel == 1) ? k : v;
    gemm_body_h(xh, W, C, freqs, m0, n0, wsel < 2, true, smemh);
}

__global__ __launch_bounds__(512, 1) void gemm_proj(const __half* __restrict__ attnh,
                                                    const __half* __restrict__ wh,
                                                    float* __restrict__ C) {
    extern __shared__ __half smemh[];
    gemm_body_h(attnh, wh + (size_t)3 * CMODEL * CMODEL, C, nullptr,
                blockIdx.y * 256, blockIdx.x * 128, false, false, smemh);
}

// ---------------------------------------------------------------------------
// Tensor-core flash-attention (R9 structure, tf32 cvt-free); attn out = half.
// ---------------------------------------------------------------------------
#define APAD 68
#define ATILE (64 * APAD)
#define ASMEM_FLOATS (4 * ATILE + 128 * APAD)

__global__ __launch_bounds__(256, 1) void flash_attn_mma(const float* __restrict__ Q,
                                                         const float* __restrict__ K,
                                                         const float* __restrict__ V,
                                                         __half* __restrict__ O) {
    extern __shared__ float sm[];
    float* Ksm[2] = { sm,             sm + 2 * ATILE };
    float* Vsm[2] = { sm + ATILE,     sm + 3 * ATILE };
    float* Ps = sm + 4 * ATILE;

    const int tid  = threadIdx.x;
    const int lane = tid & 31;
    const int wid  = tid >> 5;
    const int g    = lane >> 2;
    const int tg   = lane & 3;

    const int qb = (int)gridDim.x - 1 - (int)blockIdx.x;
    const int h  = blockIdx.y;
    const int b  = blockIdx.z;
    const int q0 = qb * 128;
    const int wrow = wid * 16;
    const int r0g = q0 + wrow + g;
    const int r1g = r0g + 8;

    const float scale = 0.125f;   // pow2: tf32-exact scaling
    uint32_t qf[8][4];
    {
        const float* q0p = Q + (((size_t)b * SEQ + r0g) * NHEAD + h) * HDIM;
        const float* q1p = Q + (((size_t)b * SEQ + r1g) * NHEAD + h) * HDIM;
#pragma unroll
        for (int ks = 0; ks < 8; ks++) {
            const int kc = ks * 8 + tg;
            qf[ks][0] = __float_as_uint(q0p[kc] * scale);
            qf[ks][1] = __float_as_uint(q1p[kc] * scale);
            qf[ks][2] = __float_as_uint(q0p[kc + 4] * scale);
            qf[ks][3] = __float_as_uint(q1p[kc + 4] * scale);
        }
    }

    float of[8][4];
#pragma unroll
    for (int nt = 0; nt < 8; nt++)
#pragma unroll
        for (int r = 0; r < 4; r++) of[nt][r] = 0.0f;
    float mrow[2] = { -1e30f, -1e30f };
    float lrow[2] = { 0.0f, 0.0f };

    const int ntiles = (q0 + 128) / 64;

    const uint32_t ks0 = smem_u32(Ksm[0]);
    const uint32_t vs0 = smem_u32(Vsm[0]);
    const uint32_t stageB = 2 * ATILE * 4;

    auto prefetch = [&](int t, int s) {
        const int kt = t * 64;
#pragma unroll
        for (int i = 0; i < 4; i++) {
            const int f = tid + 256 * i;
            const int row = f >> 4;
            const int c4 = (f & 15) * 4;
            const size_t gsrc = (((size_t)b * SEQ + kt + row) * NHEAD + h) * HDIM + c4;
            const uint32_t soff = s * stageB + (row * APAD + c4) * 4;
            cp_async16(ks0 + soff, &K[gsrc]);
            cp_async16(vs0 + soff, &V[gsrc]);
        }
    };

    prefetch(0, 0);
    CP_COMMIT();

    for (int t = 0; t < ntiles; t++) {
        const int kt = t * 64;
        if (t + 1 < ntiles) {
            prefetch(t + 1, (t + 1) & 1);
            CP_COMMIT();
            CP_WAIT(1);
        } else {
            CP_WAIT(0);
        }
        __syncthreads();

        const bool skip = kt > q0 + wrow + 15;
        if (!skip) {
            const float* kb = Ksm[t & 1];
            const float* vb = Vsm[t & 1];

            float sacc[8][4];
#pragma unroll
            for (int nt = 0; nt < 8; nt++)
#pragma unroll
                for (int r = 0; r < 4; r++) sacc[nt][r] = 0.0f;

#pragma unroll
            for (int ks = 0; ks < 8; ks++) {
                const int kc = ks * 8 + tg;
#pragma unroll
                for (int nt = 0; nt < 8; nt++) {
                    uint32_t bf[2];
                    bf[0] = __float_as_uint(kb[(nt * 8 + g) * APAD + kc]);
                    bf[1] = __float_as_uint(kb[(nt * 8 + g) * APAD + kc + 4]);
                    mma_tf32(sacc[nt], qf[ks], bf);
                }
            }

            if (kt + 63 > q0 + wrow) {
#pragma unroll
                for (int nt = 0; nt < 8; nt++) {
                    const int c = kt + nt * 8 + 2 * tg;
                    if (c > r0g)     sacc[nt][0] = -1e30f;
                    if (c + 1 > r0g) sacc[nt][1] = -1e30f;
                    if (c > r1g)     sacc[nt][2] = -1e30f;
                    if (c + 1 > r1g) sacc[nt][3] = -1e30f;
                }
            }

            float rmax0 = -1e30f, rmax1 = -1e30f;
#pragma unroll
            for (int nt = 0; nt < 8; nt++) {
                rmax0 = fmaxf(rmax0, fmaxf(sacc[nt][0], sacc[nt][1]));
                rmax1 = fmaxf(rmax1, fmaxf(sacc[nt][2], sacc[nt][3]));
            }
            rmax0 = fmaxf(rmax0, __shfl_xor_sync(0xffffffff, rmax0, 1));
            rmax0 = fmaxf(rmax0, __shfl_xor_sync(0xffffffff, rmax0, 2));
            rmax1 = fmaxf(rmax1, __shfl_xor_sync(0xffffffff, rmax1, 1));
            rmax1 = fmaxf(rmax1, __shfl_xor_sync(0xffffffff, rmax1, 2));

            const float mn0 = fmaxf(mrow[0], rmax0);
            const float mn1 = fmaxf(mrow[1], rmax1);
            const float corr0 = __expf(mrow[0] - mn0);
            const float corr1 = __expf(mrow[1] - mn1);
            mrow[0] = mn0; mrow[1] = mn1;

            float rs0 = 0.0f, rs1 = 0.0f;
            float* p0row = &Ps[(wrow + g) * APAD + 2 * tg];
            float* p1row = &Ps[(wrow + g + 8) * APAD + 2 * tg];
#pragma unroll
            for (int nt = 0; nt < 8; nt++) {
                const float e0 = __expf(sacc[nt][0] - mn0);
                const float e1 = __expf(sacc[nt][1] - mn0);
                const float e2 = __expf(sacc[nt][2] - mn1);
                const float e3 = __expf(sacc[nt][3] - mn1);
                rs0 += e0 + e1;
                rs1 += e2 + e3;
                *reinterpret_cast<float2*>(p0row + nt * 8) =
                    make_float2(__uint_as_float(f2tf32(e0)), __uint_as_float(f2tf32(e1)));
                *reinterpret_cast<float2*>(p1row + nt * 8) =
                    make_float2(__uint_as_float(f2tf32(e2)), __uint_as_float(f2tf32(e3)));
            }
            rs0 += __shfl_xor_sync(0xffffffff, rs0, 1);
            rs0 += __shfl_xor_sync(0xffffffff, rs0, 2);
            rs1 += __shfl_xor_sync(0xffffffff, rs1, 1);
            rs1 += __shfl_xor_sync(0xffffffff, rs1, 2);
            lrow[0] = lrow[0] * corr0 + rs0;
            lrow[1] = lrow[1] * corr1 + rs1;

#pragma unroll
            for (int nt = 0; nt < 8; nt++) {
                of[nt][0] *= corr0; of[nt][1] *= corr0;
                of[nt][2] *= corr1; of[nt][3] *= corr1;
            }
            __syncwarp();

#pragma unroll
            for (int ks = 0; ks < 8; ks++) {
                const int kc = ks * 8 + tg;
                uint32_t a[4];
                a[0] = __float_as_uint(Ps[(wrow + g) * APAD + kc]);
                a[1] = __float_as_uint(Ps[(wrow + g + 8) * APAD + kc]);
                a[2] = __float_as_uint(Ps[(wrow + g) * APAD + kc + 4]);
                a[3] = __float_as_uint(Ps[(wrow + g + 8) * APAD + kc + 4]);
#pragma unroll
                for (int nt = 0; nt < 8; nt++) {
                    uint32_t bf[2];
                    bf[0] = __float_as_uint(vb[kc * APAD + nt * 8 + g]);
                    bf[1] = __float_as_uint(vb[(kc + 4) * APAD + nt * 8 + g]);
                    mma_tf32(of[nt], a, bf);
                }
            }
        }
        __syncthreads();
    }

    // epilogue: write attn as half (coalesced half2 pairs)
    const float inv0 = 1.0f / lrow[0];
    const float inv1 = 1.0f / lrow[1];
    __half* o0 = O + (((size_t)b * SEQ + r0g) * NHEAD + h) * HDIM;
    __half* o1 = O + (((size_t)b * SEQ + r1g) * NHEAD + h) * HDIM;
#pragma unroll
    for (int nt = 0; nt < 8; nt++) {
        const int col = nt * 8 + 2 * tg;
        *reinterpret_cast<__half2*>(o0 + col) =
            __floats2half2_rn(of[nt][0] * inv0, of[nt][1] * inv0);
        *reinterpret_cast<__half2*>(o1 + col) =
            __floats2half2_rn(of[nt][2] * inv1, of[nt][3] * inv1);
    }
}

// ---------------------------------------------------------------------------
// kernel_launch
// ---------------------------------------------------------------------------
extern "C" void kernel_launch(void* const* d_in, const int* in_sizes, int n_in,
                              void* d_out, int out_size) {
    const float* x     = (const float*)d_in[0];
    const float* freqs = (const float*)d_in[1];
    const float* Wq    = (const float*)d_in[2];
    const float* Wk    = (const float*)d_in[3];
    const float* Wv    = (const float*)d_in[4];
    const float* Wo    = (const float*)d_in[5];
    float* out = (float*)d_out;

    float *q = nullptr, *k = nullptr, *v = nullptr;
    __half *attnh = nullptr, *xh = nullptr, *wh = nullptr;
    cudaGetSymbolAddress((void**)&q,     g_q);
    cudaGetSymbolAddress((void**)&k,     g_k);
    cudaGetSymbolAddress((void**)&v,     g_v);
    cudaGetSymbolAddress((void**)&attnh, g_attnh);
    cudaGetSymbolAddress((void**)&xh,    g_xh);
    cudaGetSymbolAddress((void**)&wh,    g_wh);

    cudaFuncSetAttribute(gemm_qkv,  cudaFuncAttributeMaxDynamicSharedMemorySize, GH_SMEM_BYTES);
    cudaFuncSetAttribute(gemm_proj, cudaFuncAttributeMaxDynamicSharedMemorySize, GH_SMEM_BYTES);
    const int asmem = ASMEM_FLOATS * sizeof(float);    // 104448
    cudaFuncSetAttribute(flash_attn_mma, cudaFuncAttributeMaxDynamicSharedMemorySize, asmem);

    // Prepass: x + 4 weight matrices to half
    {
        const int nx = MROWS * CMODEL;
        const int nw = CMODEL * CMODEL;
        to_half<<<nx / (256 * 8), 256>>>(x, xh, nx);
        to_half<<<nw / (256 * 8), 256>>>(Wq, wh + 0 * (size_t)nw, nw);
        to_half<<<nw / (256 * 8), 256>>>(Wk, wh + 1 * (size_t)nw, nw);
        to_half<<<nw / (256 * 8), 256>>>(Wv, wh + 2 * (size_t)nw, nw);
        to_half<<<nw / (256 * 8), 256>>>(Wo, wh + 3 * (size_t)nw, nw);
    }

    gemm_qkv<<<dim3(24, MROWS / 256), 512, GH_SMEM_BYTES>>>(xh, wh, q, k, v, freqs);

    {
        dim3 agrid(SEQ / 128, NHEAD, BATCH);
        flash_attn_mma<<<agrid, 256, asmem>>>(q, k, v, attnh);
    }

    gemm_proj<<<dim3(CMODEL / 128, MROWS / 256), 512, GH_SMEM_BYTES>>>(attnh, wh, out);
}

// round 12
// speedup vs baseline: 1.7560x; 1.4340x over previous
#include <cuda_runtime.h>
#include <cuda_fp16.h>
#include <cstdint>
#include <math.h>

// Problem constants
#define BATCH 2
#define SEQ   2048
#define CMODEL 1024
#define NHEAD 16
#define HDIM  64
#define MROWS (BATCH * SEQ)   // 4096

// ---------------------------------------------------------------------------
// Scratch
// ---------------------------------------------------------------------------
__device__ __half g_qh[MROWS * CMODEL];
__device__ __half g_kh[MROWS * CMODEL];
__device__ __half g_vh[MROWS * CMODEL];
__device__ __half g_attnh[MROWS * CMODEL];
__device__ __half g_xh[MROWS * CMODEL];
__device__ __half g_wh[4 * CMODEL * CMODEL];   // Wq,Wk,Wv,Wo in half

// ---------------------------------------------------------------------------
// Helpers
// ---------------------------------------------------------------------------
__device__ __forceinline__ uint32_t smem_u32(const void* p) {
    uint32_t a;
    asm("{ .reg .u64 t; cvta.to.shared.u64 t, %1; cvt.u32.u64 %0, t; }" : "=r"(a) : "l"(p));
    return a;
}
__device__ __forceinline__ void cp_async16(uint32_t s, const void* g) {
    asm volatile("cp.async.ca.shared.global [%0], [%1], 16;" :: "r"(s), "l"(g));
}
#define CP_COMMIT()  asm volatile("cp.async.commit_group;" ::: "memory")
#define CP_WAIT(N)   asm volatile("cp.async.wait_group %0;" :: "n"(N) : "memory")

__device__ __forceinline__ void mma_f16(float (&d)[4], const uint32_t (&a)[4],
                                        const uint32_t (&b)[2]) {
    asm volatile(
        "mma.sync.aligned.m16n8k16.row.col.f32.f16.f16.f32 "
        "{%0,%1,%2,%3}, {%4,%5,%6,%7}, {%8,%9}, {%0,%1,%2,%3};"
        : "+f"(d[0]), "+f"(d[1]), "+f"(d[2]), "+f"(d[3])
        : "r"(a[0]), "r"(a[1]), "r"(a[2]), "r"(a[3]), "r"(b[0]), "r"(b[1]));
}
__device__ __forceinline__ void ldsm_x2_trans(uint32_t& r0, uint32_t& r1, uint32_t addr) {
    asm volatile("ldmatrix.sync.aligned.m8n8.x2.trans.shared.b16 {%0,%1}, [%2];"
                 : "=r"(r0), "=r"(r1) : "r"(addr));
}

// ---------------------------------------------------------------------------
// Prepass: fp32 -> fp16
// ---------------------------------------------------------------------------
__global__ void to_half(const float* __restrict__ src, __half* __restrict__ dst,
                        int n) {
    int i = (blockIdx.x * 256 + threadIdx.x) * 8;
    if (i >= n) return;
    float4 v0 = *reinterpret_cast<const float4*>(src + i);
    float4 v1 = *reinterpret_cast<const float4*>(src + i + 4);
    __half2 h[4];
    h[0] = __floats2half2_rn(v0.x, v0.y);
    h[1] = __floats2half2_rn(v0.z, v0.w);
    h[2] = __floats2half2_rn(v1.x, v1.y);
    h[3] = __floats2half2_rn(v1.z, v1.w);
    *reinterpret_cast<uint2*>(dst + i)     = *reinterpret_cast<uint2*>(&h[0]);
    *reinterpret_cast<uint2*>(dst + i + 4) = *reinterpret_cast<uint2*>(&h[2]);
}

// ---------------------------------------------------------------------------
// FP16 mma.sync GEMM body: C = A * W^T, fp32 accum. Output to float* OR half*.
// CTA tile 256x128, BK=32, 512 threads, warp tile 64x32.
// ---------------------------------------------------------------------------
#define BK 32
#define KSTH 40
#define ATH (256 * KSTH)
#define WTH (128 * KSTH)
#define STAGEH (ATH + WTH)
#define GH_SMEM_BYTES (2 * STAGEH * 2)   // 61440

__device__ __forceinline__ void gemm_body_h(const __half* __restrict__ A,
                                            const __half* __restrict__ W,
                                            float* __restrict__ Cf,
                                            __half* __restrict__ Ch,
                                            const float* __restrict__ freqs,
                                            int m0, int n0, bool rope,
                                            __half* smem) {
    const int K = CMODEL, N = CMODEL;
    __half* As[2] = { smem,         smem + STAGEH };
    __half* Ws[2] = { smem + ATH,   smem + STAGEH + ATH };

    const int tid  = threadIdx.x;
    const int lane = tid & 31;
    const int wid  = tid >> 5;
    const int g    = lane >> 2;
    const int tg   = lane & 3;
    const int wm   = (wid & 3) * 64;
    const int wn   = (wid >> 2) * 32;

    float acc[4][4][4];
#pragma unroll
    for (int mt = 0; mt < 4; mt++)
#pragma unroll
        for (int nt = 0; nt < 4; nt++)
#pragma unroll
            for (int r = 0; r < 4; r++) acc[mt][nt][r] = 0.0f;

    const int ntiles = K / BK;

    auto load_tile = [&](int kt, int stg) {
        const int ko = kt * BK;
#pragma unroll
        for (int i = 0; i < 2; i++) {
            const int f = tid + 512 * i;
            const int row = f >> 2;
            const int c8 = (f & 3) * 8;
            cp_async16(smem_u32(&As[stg][row * KSTH + c8]),
                       &A[(size_t)(m0 + row) * K + ko + c8]);
        }
        {
            const int row = tid >> 2;
            const int c8 = (tid & 3) * 8;
            cp_async16(smem_u32(&Ws[stg][row * KSTH + c8]),
                       &W[(size_t)(n0 + row) * K + ko + c8]);
        }
    };

    load_tile(0, 0);
    CP_COMMIT();

    for (int kt = 0; kt < ntiles; kt++) {
        const int buf = kt & 1;
        if (kt + 1 < ntiles) {
            load_tile(kt + 1, (kt + 1) & 1);
            CP_COMMIT();
            CP_WAIT(1);
        } else {
            CP_WAIT(0);
        }
        __syncthreads();

        const __half* at = As[buf];
        const __half* wt = Ws[buf];
#pragma unroll
        for (int ks = 0; ks < 2; ks++) {
            const int kc = ks * 16 + 2 * tg;
            uint32_t a[4][4];
#pragma unroll
            for (int mt = 0; mt < 4; mt++) {
                const int r0 = (wm + mt * 16 + g) * KSTH;
                a[mt][0] = *reinterpret_cast<const uint32_t*>(at + r0 + kc);
                a[mt][1] = *reinterpret_cast<const uint32_t*>(at + r0 + 8 * KSTH + kc);
                a[mt][2] = *reinterpret_cast<const uint32_t*>(at + r0 + kc + 8);
                a[mt][3] = *reinterpret_cast<const uint32_t*>(at + r0 + 8 * KSTH + kc + 8);
            }
            uint32_t b[4][2];
#pragma unroll
            for (int nt = 0; nt < 4; nt++) {
                const int r0 = (wn + nt * 8 + g) * KSTH;
                b[nt][0] = *reinterpret_cast<const uint32_t*>(wt + r0 + kc);
                b[nt][1] = *reinterpret_cast<const uint32_t*>(wt + r0 + kc + 8);
            }
#pragma unroll
            for (int mt = 0; mt < 4; mt++)
#pragma unroll
                for (int nt = 0; nt < 4; nt++)
                    mma_f16(acc[mt][nt], a[mt], b[nt]);
        }
        __syncthreads();
    }

    // epilogue: optional fused RoPE; half or float output
#pragma unroll
    for (int mt = 0; mt < 4; mt++) {
        const int row = m0 + wm + mt * 16 + g;
        const int t0 = row & (SEQ - 1);
        const int t1 = (row + 8) & (SEQ - 1);
#pragma unroll
        for (int nt = 0; nt < 4; nt++) {
            const int col = n0 + wn + nt * 8 + 2 * tg;
            float2 v0 = make_float2(acc[mt][nt][0], acc[mt][nt][1]);
            float2 v1 = make_float2(acc[mt][nt][2], acc[mt][nt][3]);
            if (rope) {
                const int fo = (col & 62);
                float cc0 = freqs[t0 * HDIM + fo], ss0 = freqs[t0 * HDIM + fo + 1];
                float cc1 = freqs[t1 * HDIM + fo], ss1 = freqs[t1 * HDIM + fo + 1];
                v0 = make_float2(v0.x * cc0 - v0.y * ss0, v0.x * ss0 + v0.y * cc0);
                v1 = make_float2(v1.x * cc1 - v1.y * ss1, v1.x * ss1 + v1.y * cc1);
            }
            if (Ch) {
                *reinterpret_cast<__half2*>(&Ch[(size_t)row * N + col]) =
                    __floats2half2_rn(v0.x, v0.y);
                *reinterpret_cast<__half2*>(&Ch[(size_t)(row + 8) * N + col]) =
                    __floats2half2_rn(v1.x, v1.y);
            } else {
                *reinterpret_cast<float2*>(&Cf[(size_t)row * N + col]) = v0;
                *reinterpret_cast<float2*>(&Cf[(size_t)(row + 8) * N + col]) = v1;
            }
        }
    }
}

// Fused QKV + RoPE, half outputs
__global__ __launch_bounds__(512, 1) void gemm_qkv(const __half* __restrict__ xh,
                                                   const __half* __restrict__ wh,
                                                   __half* __restrict__ q,
                                                   __half* __restrict__ k,
                                                   __half* __restrict__ v,
                                                   const float* __restrict__ freqs) {
    extern __shared__ __half smemh[];
    const int wsel = blockIdx.x >> 3;
    const int n0 = (blockIdx.x & 7) * 128;
    const int m0 = blockIdx.y * 256;
    const __half* W = wh + (size_t)wsel * CMODEL * CMODEL;
    __half* C = (wsel == 0) ? q : (wsel == 1) ? k : v;
    gemm_body_h(xh, W, nullptr, C, freqs, m0, n0, wsel < 2, smemh);
}

__global__ __launch_bounds__(512, 1) void gemm_proj(const __half* __restrict__ attnh,
                                                    const __half* __restrict__ wh,
                                                    float* __restrict__ C) {
    extern __shared__ __half smemh[];
    gemm_body_h(attnh, wh + (size_t)3 * CMODEL * CMODEL, C, nullptr, nullptr,
                blockIdx.y * 256, blockIdx.x * 128, false, smemh);
}

// ---------------------------------------------------------------------------
// FP16 tensor-core flash-attention, causal.
// CTA: 128 queries x 1 head, 8 warps x 16 rows, 64-key tiles.
// K/V half in SMEM (stride 72 halves); V consumed via ldmatrix.x2.trans;
// P staged as half. fp32 softmax state and O accumulators.
// ---------------------------------------------------------------------------
#define VROW 72                          // halves per SMEM row
#define HTILE (64 * VROW)                // halves per K or V tile (4608)
#define HSMEM_BYTES (4 * HTILE * 2 + 128 * VROW * 2)   // 36864 + 18432 = 55296

__global__ __launch_bounds__(256, 2) void flash_attn_mma(const __half* __restrict__ Q,
                                                         const __half* __restrict__ K,
                                                         const __half* __restrict__ V,
                                                         __half* __restrict__ O) {
    extern __shared__ __half smh[];
    __half* Ksm[2] = { smh,              smh + 2 * HTILE };
    __half* Vsm[2] = { smh + HTILE,      smh + 3 * HTILE };
    __half* Ps = smh + 4 * HTILE;        // [128][VROW]

    const int tid  = threadIdx.x;
    const int lane = tid & 31;
    const int wid  = tid >> 5;
    const int g    = lane >> 2;
    const int tg   = lane & 3;

    const int qb = (int)gridDim.x - 1 - (int)blockIdx.x;
    const int h  = blockIdx.y;
    const int b  = blockIdx.z;
    const int q0 = qb * 128;
    const int wrow = wid * 16;
    const int r0g = q0 + wrow + g;
    const int r1g = r0g + 8;

    // Q fragments: half2 pairs, pre-scaled by 0.125 (pow2, exact)
    const __half2 s2 = __half2half2(__float2half(0.125f));
    uint32_t qf[4][4];
    {
        const __half* q0p = Q + (((size_t)b * SEQ + r0g) * NHEAD + h) * HDIM;
        const __half* q1p = Q + (((size_t)b * SEQ + r1g) * NHEAD + h) * HDIM;
#pragma unroll
        for (int ks = 0; ks < 4; ks++) {
            const int kc = ks * 16 + 2 * tg;
            __half2 h0 = __hmul2(*reinterpret_cast<const __half2*>(q0p + kc), s2);
            __half2 h1 = __hmul2(*reinterpret_cast<const __half2*>(q1p + kc), s2);
            __half2 h2 = __hmul2(*reinterpret_cast<const __half2*>(q0p + kc + 8), s2);
            __half2 h3 = __hmul2(*reinterpret_cast<const __half2*>(q1p + kc + 8), s2);
            qf[ks][0] = *reinterpret_cast<uint32_t*>(&h0);
            qf[ks][1] = *reinterpret_cast<uint32_t*>(&h1);
            qf[ks][2] = *reinterpret_cast<uint32_t*>(&h2);
            qf[ks][3] = *reinterpret_cast<uint32_t*>(&h3);
        }
    }

    float of[8][4];
#pragma unroll
    for (int nt = 0; nt < 8; nt++)
#pragma unroll
        for (int r = 0; r < 4; r++) of[nt][r] = 0.0f;
    float mrow[2] = { -1e30f, -1e30f };
    float lrow[2] = { 0.0f, 0.0f };

    const int ntiles = (q0 + 128) / 64;

    const uint32_t ks0 = smem_u32(Ksm[0]);
    const uint32_t vs0 = smem_u32(Vsm[0]);
    const uint32_t stageB = 2 * HTILE * 2;   // bytes between stages

    auto prefetch = [&](int t, int s) {
        const int kt = t * 64;
#pragma unroll
        for (int i = 0; i < 2; i++) {
            const int f = tid + 256 * i;       // 0..511
            const int row = f >> 3;            // 0..63
            const int c8 = (f & 7) * 8;        // half offset
            const size_t gsrc = (((size_t)b * SEQ + kt + row) * NHEAD + h) * HDIM + c8;
            const uint32_t soff = s * stageB + (row * VROW + c8) * 2;
            cp_async16(ks0 + soff, &K[gsrc]);
            cp_async16(vs0 + soff, &V[gsrc]);
        }
    };

    prefetch(0, 0);
    CP_COMMIT();

    for (int t = 0; t < ntiles; t++) {
        const int kt = t * 64;
        if (t + 1 < ntiles) {
            prefetch(t + 1, (t + 1) & 1);
            CP_COMMIT();
            CP_WAIT(1);
        } else {
            CP_WAIT(0);
        }
        __syncthreads();

        const bool skip = kt > q0 + wrow + 15;
        if (!skip) {
            const __half* kb = Ksm[t & 1];
            const uint32_t vbase = vs0 + (t & 1) * stageB;

            // ---- S = Q * K^T (fp16 mma, fp32 accum) ----
            float sacc[8][4];
#pragma unroll
            for (int nt = 0; nt < 8; nt++)
#pragma unroll
                for (int r = 0; r < 4; r++) sacc[nt][r] = 0.0f;

#pragma unroll
            for (int ks = 0; ks < 4; ks++) {
                const int kc = ks * 16 + 2 * tg;
#pragma unroll
                for (int nt = 0; nt < 8; nt++) {
                    const __half* kr = kb + (nt * 8 + g) * VROW + kc;
                    uint32_t bf[2];
                    bf[0] = *reinterpret_cast<const uint32_t*>(kr);
                    bf[1] = *reinterpret_cast<const uint32_t*>(kr + 8);
                    mma_f16(sacc[nt], qf[ks], bf);
                }
            }

            // ---- causal mask ----
            if (kt + 63 > q0 + wrow) {
#pragma unroll
                for (int nt = 0; nt < 8; nt++) {
                    const int c = kt + nt * 8 + 2 * tg;
                    if (c > r0g)     sacc[nt][0] = -1e30f;
                    if (c + 1 > r0g) sacc[nt][1] = -1e30f;
                    if (c > r1g)     sacc[nt][2] = -1e30f;
                    if (c + 1 > r1g) sacc[nt][3] = -1e30f;
                }
            }

            // ---- online softmax (fp32) ----
            float rmax0 = -1e30f, rmax1 = -1e30f;
#pragma unroll
            for (int nt = 0; nt < 8; nt++) {
                rmax0 = fmaxf(rmax0, fmaxf(sacc[nt][0], sacc[nt][1]));
                rmax1 = fmaxf(rmax1, fmaxf(sacc[nt][2], sacc[nt][3]));
            }
            rmax0 = fmaxf(rmax0, __shfl_xor_sync(0xffffffff, rmax0, 1));
            rmax0 = fmaxf(rmax0, __shfl_xor_sync(0xffffffff, rmax0, 2));
            rmax1 = fmaxf(rmax1, __shfl_xor_sync(0xffffffff, rmax1, 1));
            rmax1 = fmaxf(rmax1, __shfl_xor_sync(0xffffffff, rmax1, 2));

            const float mn0 = fmaxf(mrow[0], rmax0);
            const float mn1 = fmaxf(mrow[1], rmax1);
            const float corr0 = __expf(mrow[0] - mn0);
            const float corr1 = __expf(mrow[1] - mn1);
            mrow[0] = mn0; mrow[1] = mn1;

            float rs0 = 0.0f, rs1 = 0.0f;
            __half* p0row = Ps + (wrow + g) * VROW + 2 * tg;
            __half* p1row = Ps + (wrow + g + 8) * VROW + 2 * tg;
#pragma unroll
            for (int nt = 0; nt < 8; nt++) {
                const float e0 = __expf(sacc[nt][0] - mn0);
                const float e1 = __expf(sacc[nt][1] - mn0);
                const float e2 = __expf(sacc[nt][2] - mn1);
                const float e3 = __expf(sacc[nt][3] - mn1);
                rs0 += e0 + e1;
                rs1 += e2 + e3;
                *reinterpret_cast<__half2*>(p0row + nt * 8) = __floats2half2_rn(e0, e1);
                *reinterpret_cast<__half2*>(p1row + nt * 8) = __floats2half2_rn(e2, e3);
            }
            rs0 += __shfl_xor_sync(0xffffffff, rs0, 1);
            rs0 += __shfl_xor_sync(0xffffffff, rs0, 2);
            rs1 += __shfl_xor_sync(0xffffffff, rs1, 1);
            rs1 += __shfl_xor_sync(0xffffffff, rs1, 2);
            lrow[0] = lrow[0] * corr0 + rs0;
            lrow[1] = lrow[1] * corr1 + rs1;

#pragma unroll
            for (int nt = 0; nt < 8; nt++) {
                of[nt][0] *= corr0; of[nt][1] *= corr0;
                of[nt][2] *= corr1; of[nt][3] *= corr1;
            }
            __syncwarp();

            // ---- O += P * V (V via ldmatrix.trans) ----
#pragma unroll
            for (int ks = 0; ks < 4; ks++) {
                const int kc = ks * 16 + 2 * tg;
                uint32_t a[4];
                a[0] = *reinterpret_cast<const uint32_t*>(Ps + (wrow + g) * VROW + kc);
                a[1] = *reinterpret_cast<const uint32_t*>(Ps + (wrow + g + 8) * VROW + kc);
                a[2] = *reinterpret_cast<const uint32_t*>(Ps + (wrow + g) * VROW + kc + 8);
                a[3] = *reinterpret_cast<const uint32_t*>(Ps + (wrow + g + 8) * VROW + kc + 8);
                // ldmatrix row address: lane l (0..15) -> V row ks*16 + l
                const uint32_t lrowaddr = vbase + ((ks * 16 + (lane & 15)) * VROW) * 2;
#pragma unroll
                for (int nt = 0; nt < 8; nt++) {
                    uint32_t bf[2];
                    ldsm_x2_trans(bf[0], bf[1], lrowaddr + nt * 16);
                    mma_f16(of[nt], a, bf);
                }
            }
        }
        __syncthreads();
    }

    // ---- epilogue: half2 coalesced output ----
    const float inv0 = 1.0f / lrow[0];
    const float inv1 = 1.0f / lrow[1];
    __half* o0 = O + (((size_t)b * SEQ + r0g) * NHEAD + h) * HDIM;
    __half* o1 = O + (((size_t)b * SEQ + r1g) * NHEAD + h) * HDIM;
#pragma unroll
    for (int nt = 0; nt < 8; nt++) {
        const int col = nt * 8 + 2 * tg;
        *reinterpret_cast<__half2*>(o0 + col) =
            __floats2half2_rn(of[nt][0] * inv0, of[nt][1] * inv0);
        *reinterpret_cast<__half2*>(o1 + col) =
            __floats2half2_rn(of[nt][2] * inv1, of[nt][3] * inv1);
    }
}

// ---------------------------------------------------------------------------
// kernel_launch
// ---------------------------------------------------------------------------
extern "C" void kernel_launch(void* const* d_in, const int* in_sizes, int n_in,
                              void* d_out, int out_size) {
    const float* x     = (const float*)d_in[0];
    const float* freqs = (const float*)d_in[1];
    const float* Wq    = (const float*)d_in[2];
    const float* Wk    = (const float*)d_in[3];
    const float* Wv    = (const float*)d_in[4];
    const float* Wo    = (const float*)d_in[5];
    float* out = (float*)d_out;

    __half *qh = nullptr, *kh = nullptr, *vh = nullptr;
    __half *attnh = nullptr, *xh = nullptr, *wh = nullptr;
    cudaGetSymbolAddress((void**)&qh,    g_qh);
    cudaGetSymbolAddress((void**)&kh,    g_kh);
    cudaGetSymbolAddress((void**)&vh,    g_vh);
    cudaGetSymbolAddress((void**)&attnh, g_attnh);
    cudaGetSymbolAddress((void**)&xh,    g_xh);
    cudaGetSymbolAddress((void**)&wh,    g_wh);

    cudaFuncSetAttribute(gemm_qkv,  cudaFuncAttributeMaxDynamicSharedMemorySize, GH_SMEM_BYTES);
    cudaFuncSetAttribute(gemm_proj, cudaFuncAttributeMaxDynamicSharedMemorySize, GH_SMEM_BYTES);
    cudaFuncSetAttribute(flash_attn_mma, cudaFuncAttributeMaxDynamicSharedMemorySize, HSMEM_BYTES);

    // Prepass: x + 4 weight matrices to half
    {
        const int nx = MROWS * CMODEL;
        const int nw = CMODEL * CMODEL;
        to_half<<<nx / (256 * 8), 256>>>(x, xh, nx);
        to_half<<<nw / (256 * 8), 256>>>(Wq, wh + 0 * (size_t)nw, nw);
        to_half<<<nw / (256 * 8), 256>>>(Wk, wh + 1 * (size_t)nw, nw);
        to_half<<<nw / (256 * 8), 256>>>(Wv, wh + 2 * (size_t)nw, nw);
        to_half<<<nw / (256 * 8), 256>>>(Wo, wh + 3 * (size_t)nw, nw);
    }

    gemm_qkv<<<dim3(24, MROWS / 256), 512, GH_SMEM_BYTES>>>(xh, wh, qh, kh, vh, freqs);

    {
        dim3 agrid(SEQ / 128, NHEAD, BATCH);
        flash_attn_mma<<<agrid, 256, HSMEM_BYTES>>>(qh, kh, vh, attnh);
    }

    gemm_proj<<<dim3(CMODEL / 128, MROWS / 256), 512, GH_SMEM_BYTES>>>(attnh, wh, out);
}

// round 13
// speedup vs baseline: 1.7661x; 1.0058x over previous
#include <cuda_runtime.h>
#include <cuda_fp16.h>
#include <cstdint>
#include <math.h>

// Problem constants
#define BATCH 2
#define SEQ   2048
#define CMODEL 1024
#define NHEAD 16
#define HDIM  64
#define MROWS (BATCH * SEQ)   // 4096

// ---------------------------------------------------------------------------
// Scratch
// ---------------------------------------------------------------------------
__device__ __half g_qh[MROWS * CMODEL];
__device__ __half g_kh[MROWS * CMODEL];
__device__ __half g_vh[MROWS * CMODEL];
__device__ __half g_attnh[MROWS * CMODEL];
__device__ __half g_xh[MROWS * CMODEL];
__device__ __half g_wh[4 * CMODEL * CMODEL];   // Wq,Wk,Wv,Wo in half

// ---------------------------------------------------------------------------
// Helpers
// ---------------------------------------------------------------------------
__device__ __forceinline__ uint32_t smem_u32(const void* p) {
    uint32_t a;
    asm("{ .reg .u64 t; cvta.to.shared.u64 t, %1; cvt.u32.u64 %0, t; }" : "=r"(a) : "l"(p));
    return a;
}
__device__ __forceinline__ void cp_async16(uint32_t s, const void* g) {
    asm volatile("cp.async.ca.shared.global [%0], [%1], 16;" :: "r"(s), "l"(g));
}
#define CP_COMMIT()  asm volatile("cp.async.commit_group;" ::: "memory")
#define CP_WAIT(N)   asm volatile("cp.async.wait_group %0;" :: "n"(N) : "memory")

__device__ __forceinline__ void mma_f16(float (&d)[4], const uint32_t (&a)[4],
                                        const uint32_t (&b)[2]) {
    asm volatile(
        "mma.sync.aligned.m16n8k16.row.col.f32.f16.f16.f32 "
        "{%0,%1,%2,%3}, {%4,%5,%6,%7}, {%8,%9}, {%0,%1,%2,%3};"
        : "+f"(d[0]), "+f"(d[1]), "+f"(d[2]), "+f"(d[3])
        : "r"(a[0]), "r"(a[1]), "r"(a[2]), "r"(a[3]), "r"(b[0]), "r"(b[1]));
}
__device__ __forceinline__ void ldsm_x2_trans(uint32_t& r0, uint32_t& r1, uint32_t addr) {
    asm volatile("ldmatrix.sync.aligned.m8n8.x2.trans.shared.b16 {%0,%1}, [%2];"
                 : "=r"(r0), "=r"(r1) : "r"(addr));
}

// ---------------------------------------------------------------------------
// Fused prepass: fp32 -> fp16 for x + all four weight matrices, one launch.
// ---------------------------------------------------------------------------
__global__ void to_half_all(const float* __restrict__ x,
                            const float* __restrict__ wq,
                            const float* __restrict__ wk,
                            const float* __restrict__ wv,
                            const float* __restrict__ wo,
                            __half* __restrict__ xh,
                            __half* __restrict__ wh) {
    const long long nx = (long long)MROWS * CMODEL;     // 4M
    const long long nw = (long long)CMODEL * CMODEL;    // 1M
    long long i = (long long)(blockIdx.x * 256 + threadIdx.x) * 8;
    if (i >= nx + 4 * nw) return;

    const float* src;
    __half* dst;
    long long off;
    if (i < nx) {
        src = x; dst = xh; off = i;
    } else {
        long long j = i - nx;
        int s = (int)(j / nw);
        off = j - (long long)s * nw;
        src = (s == 0) ? wq : (s == 1) ? wk : (s == 2) ? wv : wo;
        dst = wh + (size_t)s * nw;
    }
    float4 v0 = *reinterpret_cast<const float4*>(src + off);
    float4 v1 = *reinterpret_cast<const float4*>(src + off + 4);
    __half2 h[4];
    h[0] = __floats2half2_rn(v0.x, v0.y);
    h[1] = __floats2half2_rn(v0.z, v0.w);
    h[2] = __floats2half2_rn(v1.x, v1.y);
    h[3] = __floats2half2_rn(v1.z, v1.w);
    *reinterpret_cast<uint2*>(dst + off)     = *reinterpret_cast<uint2*>(&h[0]);
    *reinterpret_cast<uint2*>(dst + off + 4) = *reinterpret_cast<uint2*>(&h[2]);
}

// ---------------------------------------------------------------------------
// FP16 mma.sync GEMM body: C = A * W^T, fp32 accum. 3-stage cp.async pipeline.
// CTA tile 256x128, BK=32, 512 threads, warp tile 64x32.
// ---------------------------------------------------------------------------
#define BK 32
#define KSTH 40
#define ATH (256 * KSTH)
#define WTH (128 * KSTH)
#define STAGEH (ATH + WTH)
#define GH_SMEM_BYTES (3 * STAGEH * 2)   // 92160

__device__ __forceinline__ void gemm_body_h(const __half* __restrict__ A,
                                            const __half* __restrict__ W,
                                            float* __restrict__ Cf,
                                            __half* __restrict__ Ch,
                                            const float* __restrict__ freqs,
                                            int m0, int n0, bool rope,
                                            __half* smem) {
    const int K = CMODEL, N = CMODEL;
    __half* As[3] = { smem, smem + STAGEH, smem + 2 * STAGEH };
    __half* Ws[3] = { smem + ATH, smem + STAGEH + ATH, smem + 2 * STAGEH + ATH };

    const int tid  = threadIdx.x;
    const int lane = tid & 31;
    const int wid  = tid >> 5;
    const int g    = lane >> 2;
    const int tg   = lane & 3;
    const int wm   = (wid & 3) * 64;
    const int wn   = (wid >> 2) * 32;

    float acc[4][4][4];
#pragma unroll
    for (int mt = 0; mt < 4; mt++)
#pragma unroll
        for (int nt = 0; nt < 4; nt++)
#pragma unroll
            for (int r = 0; r < 4; r++) acc[mt][nt][r] = 0.0f;

    const int ntiles = K / BK;   // 32

    auto load_tile = [&](int kt, int stg) {
        const int ko = kt * BK;
#pragma unroll
        for (int i = 0; i < 2; i++) {
            const int f = tid + 512 * i;
            const int row = f >> 2;
            const int c8 = (f & 3) * 8;
            cp_async16(smem_u32(&As[stg][row * KSTH + c8]),
                       &A[(size_t)(m0 + row) * K + ko + c8]);
        }
        {
            const int row = tid >> 2;
            const int c8 = (tid & 3) * 8;
            cp_async16(smem_u32(&Ws[stg][row * KSTH + c8]),
                       &W[(size_t)(n0 + row) * K + ko + c8]);
        }
    };

    load_tile(0, 0);
    CP_COMMIT();
    if (ntiles > 1) { load_tile(1, 1); CP_COMMIT(); }

    for (int kt = 0; kt < ntiles; kt++) {
        if (kt + 2 < ntiles) {
            load_tile(kt + 2, (kt + 2) % 3);
            CP_COMMIT();
            CP_WAIT(2);
        } else if (kt + 1 < ntiles) {
            CP_WAIT(1);
        } else {
            CP_WAIT(0);
        }
        __syncthreads();

        const __half* at = As[kt % 3];
        const __half* wt = Ws[kt % 3];
#pragma unroll
        for (int ks = 0; ks < 2; ks++) {
            const int kc = ks * 16 + 2 * tg;
            uint32_t a[4][4];
#pragma unroll
            for (int mt = 0; mt < 4; mt++) {
                const int r0 = (wm + mt * 16 + g) * KSTH;
                a[mt][0] = *reinterpret_cast<const uint32_t*>(at + r0 + kc);
                a[mt][1] = *reinterpret_cast<const uint32_t*>(at + r0 + 8 * KSTH + kc);
                a[mt][2] = *reinterpret_cast<const uint32_t*>(at + r0 + kc + 8);
                a[mt][3] = *reinterpret_cast<const uint32_t*>(at + r0 + 8 * KSTH + kc + 8);
            }
            uint32_t b[4][2];
#pragma unroll
            for (int nt = 0; nt < 4; nt++) {
                const int r0 = (wn + nt * 8 + g) * KSTH;
                b[nt][0] = *reinterpret_cast<const uint32_t*>(wt + r0 + kc);
                b[nt][1] = *reinterpret_cast<const uint32_t*>(wt + r0 + kc + 8);
            }
#pragma unroll
            for (int mt = 0; mt < 4; mt++)
#pragma unroll
                for (int nt = 0; nt < 4; nt++)
                    mma_f16(acc[mt][nt], a[mt], b[nt]);
        }
        __syncthreads();
    }

    // epilogue: optional fused RoPE; half or float output
#pragma unroll
    for (int mt = 0; mt < 4; mt++) {
        const int row = m0 + wm + mt * 16 + g;
        const int t0 = row & (SEQ - 1);
        const int t1 = (row + 8) & (SEQ - 1);
#pragma unroll
        for (int nt = 0; nt < 4; nt++) {
            const int col = n0 + wn + nt * 8 + 2 * tg;
            float2 v0 = make_float2(acc[mt][nt][0], acc[mt][nt][1]);
            float2 v1 = make_float2(acc[mt][nt][2], acc[mt][nt][3]);
            if (rope) {
                const int fo = (col & 62);
                float cc0 = freqs[t0 * HDIM + fo], ss0 = freqs[t0 * HDIM + fo + 1];
                float cc1 = freqs[t1 * HDIM + fo], ss1 = freqs[t1 * HDIM + fo + 1];
                v0 = make_float2(v0.x * cc0 - v0.y * ss0, v0.x * ss0 + v0.y * cc0);
                v1 = make_float2(v1.x * cc1 - v1.y * ss1, v1.x * ss1 + v1.y * cc1);
            }
            if (Ch) {
                *reinterpret_cast<__half2*>(&Ch[(size_t)row * N + col]) =
                    __floats2half2_rn(v0.x, v0.y);
                *reinterpret_cast<__half2*>(&Ch[(size_t)(row + 8) * N + col]) =
                    __floats2half2_rn(v1.x, v1.y);
            } else {
                *reinterpret_cast<float2*>(&Cf[(size_t)row * N + col]) = v0;
                *reinterpret_cast<float2*>(&Cf[(size_t)(row + 8) * N + col]) = v1;
            }
        }
    }
}

// Fused QKV + RoPE, half outputs
__global__ __launch_bounds__(512, 1) void gemm_qkv(const __half* __restrict__ xh,
                                                   const __half* __restrict__ wh,
                                                   __half* __restrict__ q,
                                                   __half* __restrict__ k,
                                                   __half* __restrict__ v,
                                                   const float* __restrict__ freqs) {
    extern __shared__ __half smemh[];
    const int wsel = blockIdx.x >> 3;
    const int n0 = (blockIdx.x & 7) * 128;
    const int m0 = blockIdx.y * 256;
    const __half* W = wh + (size_t)wsel * CMODEL * CMODEL;
    __half* C = (wsel == 0) ? q : (wsel == 1) ? k : v;
    gemm_body_h(xh, W, nullptr, C, freqs, m0, n0, wsel < 2, smemh);
}

__global__ __launch_bounds__(512, 1) void gemm_proj(const __half* __restrict__ attnh,
                                                    const __half* __restrict__ wh,
                                                    float* __restrict__ C) {
    extern __shared__ __half smemh[];
    gemm_body_h(attnh, wh + (size_t)3 * CMODEL * CMODEL, C, nullptr, nullptr,
                blockIdx.y * 256, blockIdx.x * 128, false, smemh);
}

// ---------------------------------------------------------------------------
// FP16 tensor-core flash-attention, causal. 3-stage cp.async pipeline.
// CTA: 128 queries x 1 head, 8 warps x 16 rows, 64-key tiles, 2 CTAs/SM.
// ---------------------------------------------------------------------------
#define VROW 72                          // halves per SMEM row
#define HTILE (64 * VROW)                // halves per K or V tile (4608)
#define HSMEM_BYTES (6 * HTILE * 2 + 128 * VROW * 2)   // 55296 + 18432 = 73728

__global__ __launch_bounds__(256, 2) void flash_attn_mma(const __half* __restrict__ Q,
                                                         const __half* __restrict__ K,
                                                         const __half* __restrict__ V,
                                                         __half* __restrict__ O) {
    extern __shared__ __half smh[];
    __half* Ksm[3] = { smh, smh + 2 * HTILE, smh + 4 * HTILE };
    __half* Ps = smh + 6 * HTILE;        // [128][VROW]

    const int tid  = threadIdx.x;
    const int lane = tid & 31;
    const int wid  = tid >> 5;
    const int g    = lane >> 2;
    const int tg   = lane & 3;

    const int qb = (int)gridDim.x - 1 - (int)blockIdx.x;
    const int h  = blockIdx.y;
    const int b  = blockIdx.z;
    const int q0 = qb * 128;
    const int wrow = wid * 16;
    const int r0g = q0 + wrow + g;
    const int r1g = r0g + 8;

    // Q fragments: half2 pairs, pre-scaled by 0.125 (pow2, exact)
    const __half2 s2 = __half2half2(__float2half(0.125f));
    uint32_t qf[4][4];
    {
        const __half* q0p = Q + (((size_t)b * SEQ + r0g) * NHEAD + h) * HDIM;
        const __half* q1p = Q + (((size_t)b * SEQ + r1g) * NHEAD + h) * HDIM;
#pragma unroll
        for (int ks = 0; ks < 4; ks++) {
            const int kc = ks * 16 + 2 * tg;
            __half2 h0 = __hmul2(*reinterpret_cast<const __half2*>(q0p + kc), s2);
            __half2 h1 = __hmul2(*reinterpret_cast<const __half2*>(q1p + kc), s2);
            __half2 h2 = __hmul2(*reinterpret_cast<const __half2*>(q0p + kc + 8), s2);
            __half2 h3 = __hmul2(*reinterpret_cast<const __half2*>(q1p + kc + 8), s2);
            qf[ks][0] = *reinterpret_cast<uint32_t*>(&h0);
            qf[ks][1] = *reinterpret_cast<uint32_t*>(&h1);
            qf[ks][2] = *reinterpret_cast<uint32_t*>(&h2);
            qf[ks][3] = *reinterpret_cast<uint32_t*>(&h3);
        }
    }

    float of[8][4];
#pragma unroll
    for (int nt = 0; nt < 8; nt++)
#pragma unroll
        for (int r = 0; r < 4; r++) of[nt][r] = 0.0f;
    float mrow[2] = { -1e30f, -1e30f };
    float lrow[2] = { 0.0f, 0.0f };

    const int ntiles = (q0 + 128) / 64;

    const uint32_t ks0 = smem_u32(Ksm[0]);
    const uint32_t stageB = 2 * HTILE * 2;   // bytes between stages (K+V pair)

    auto prefetch = [&](int t, int s) {
        const int kt = t * 64;
#pragma unroll
        for (int i = 0; i < 2; i++) {
            const int f = tid + 256 * i;       // 0..511
            const int row = f >> 3;            // 0..63
            const int c8 = (f & 7) * 8;        // half offset
            const size_t gsrc = (((size_t)b * SEQ + kt + row) * NHEAD + h) * HDIM + c8;
            const uint32_t soff = s * stageB + (row * VROW + c8) * 2;
            cp_async16(ks0 + soff, &K[gsrc]);
            cp_async16(ks0 + soff + HTILE * 2, &V[gsrc]);
        }
    };

    prefetch(0, 0);
    CP_COMMIT();
    if (ntiles > 1) { prefetch(1, 1); CP_COMMIT(); }

    for (int t = 0; t < ntiles; t++) {
        const int kt = t * 64;
        if (t + 2 < ntiles) {
            prefetch(t + 2, (t + 2) % 3);
            CP_COMMIT();
            CP_WAIT(2);
        } else if (t + 1 < ntiles) {
            CP_WAIT(1);
        } else {
            CP_WAIT(0);
        }
        __syncthreads();

        const bool skip = kt > q0 + wrow + 15;
        if (!skip) {
            const __half* kb = Ksm[t % 3];
            const uint32_t vbase = ks0 + (t % 3) * stageB + HTILE * 2;

            // ---- S = Q * K^T ----
            float sacc[8][4];
#pragma unroll
            for (int nt = 0; nt < 8; nt++)
#pragma unroll
                for (int r = 0; r < 4; r++) sacc[nt][r] = 0.0f;

#pragma unroll
            for (int ks = 0; ks < 4; ks++) {
                const int kc = ks * 16 + 2 * tg;
#pragma unroll
                for (int nt = 0; nt < 8; nt++) {
                    const __half* kr = kb + (nt * 8 + g) * VROW + kc;
                    uint32_t bf[2];
                    bf[0] = *reinterpret_cast<const uint32_t*>(kr);
                    bf[1] = *reinterpret_cast<const uint32_t*>(kr + 8);
                    mma_f16(sacc[nt], qf[ks], bf);
                }
            }

            // ---- causal mask ----
            if (kt + 63 > q0 + wrow) {
#pragma unroll
                for (int nt = 0; nt < 8; nt++) {
                    const int c = kt + nt * 8 + 2 * tg;
                    if (c > r0g)     sacc[nt][0] = -1e30f;
                    if (c + 1 > r0g) sacc[nt][1] = -1e30f;
                    if (c > r1g)     sacc[nt][2] = -1e30f;
                    if (c + 1 > r1g) sacc[nt][3] = -1e30f;
                }
            }

            // ---- online softmax (fp32) ----
            float rmax0 = -1e30f, rmax1 = -1e30f;
#pragma unroll
            for (int nt = 0; nt < 8; nt++) {
                rmax0 = fmaxf(rmax0, fmaxf(sacc[nt][0], sacc[nt][1]));
                rmax1 = fmaxf(rmax1, fmaxf(sacc[nt][2], sacc[nt][3]));
            }
            rmax0 = fmaxf(rmax0, __shfl_xor_sync(0xffffffff, rmax0, 1));
            rmax0 = fmaxf(rmax0, __shfl_xor_sync(0xffffffff, rmax0, 2));
            rmax1 = fmaxf(rmax1, __shfl_xor_sync(0xffffffff, rmax1, 1));
            rmax1 = fmaxf(rmax1, __shfl_xor_sync(0xffffffff, rmax1, 2));

            const float mn0 = fmaxf(mrow[0], rmax0);
            const float mn1 = fmaxf(mrow[1], rmax1);
            const float corr0 = __expf(mrow[0] - mn0);
            const float corr1 = __expf(mrow[1] - mn1);
            mrow[0] = mn0; mrow[1] = mn1;

            float rs0 = 0.0f, rs1 = 0.0f;
            __half* p0row = Ps + (wrow + g) * VROW + 2 * tg;
            __half* p1row = Ps + (wrow + g + 8) * VROW + 2 * tg;
#pragma unroll
            for (int nt = 0; nt < 8; nt++) {
                const float e0 = __expf(sacc[nt][0] - mn0);
                const float e1 = __expf(sacc[nt][1] - mn0);
                const float e2 = __expf(sacc[nt][2] - mn1);
                const float e3 = __expf(sacc[nt][3] - mn1);
                rs0 += e0 + e1;
                rs1 += e2 + e3;
                *reinterpret_cast<__half2*>(p0row + nt * 8) = __floats2half2_rn(e0, e1);
                *reinterpret_cast<__half2*>(p1row + nt * 8) = __floats2half2_rn(e2, e3);
            }
            rs0 += __shfl_xor_sync(0xffffffff, rs0, 1);
            rs0 += __shfl_xor_sync(0xffffffff, rs0, 2);
            rs1 += __shfl_xor_sync(0xffffffff, rs1, 1);
            rs1 += __shfl_xor_sync(0xffffffff, rs1, 2);
            lrow[0] = lrow[0] * corr0 + rs0;
            lrow[1] = lrow[1] * corr1 + rs1;

#pragma unroll
            for (int nt = 0; nt < 8; nt++) {
                of[nt][0] *= corr0; of[nt][1] *= corr0;
                of[nt][2] *= corr1; of[nt][3] *= corr1;
            }
            __syncwarp();

            // ---- O += P * V (V via ldmatrix.trans) ----
#pragma unroll
            for (int ks = 0; ks < 4; ks++) {
                const int kc = ks * 16 + 2 * tg;
                uint32_t a[4];
                a[0] = *reinterpret_cast<const uint32_t*>(Ps + (wrow + g) * VROW + kc);
                a[1] = *reinterpret_cast<const uint32_t*>(Ps + (wrow + g + 8) * VROW + kc);
                a[2] = *reinterpret_cast<const uint32_t*>(Ps + (wrow + g) * VROW + kc + 8);
                a[3] = *reinterpret_cast<const uint32_t*>(Ps + (wrow + g + 8) * VROW + kc + 8);
                const uint32_t lrowaddr = vbase + ((ks * 16 + (lane & 15)) * VROW) * 2;
#pragma unroll
                for (int nt = 0; nt < 8; nt++) {
                    uint32_t bf[2];
                    ldsm_x2_trans(bf[0], bf[1], lrowaddr + nt * 16);
                    mma_f16(of[nt], a, bf);
                }
            }
        }
        __syncthreads();
    }

    // ---- epilogue: half2 coalesced output ----
    const float inv0 = 1.0f / lrow[0];
    const float inv1 = 1.0f / lrow[1];
    __half* o0 = O + (((size_t)b * SEQ + r0g) * NHEAD + h) * HDIM;
    __half* o1 = O + (((size_t)b * SEQ + r1g) * NHEAD + h) * HDIM;
#pragma unroll
    for (int nt = 0; nt < 8; nt++) {
        const int col = nt * 8 + 2 * tg;
        *reinterpret_cast<__half2*>(o0 + col) =
            __floats2half2_rn(of[nt][0] * inv0, of[nt][1] * inv0);
        *reinterpret_cast<__half2*>(o1 + col) =
            __floats2half2_rn(of[nt][2] * inv1, of[nt][3] * inv1);
    }
}

// ---------------------------------------------------------------------------
// kernel_launch
// ---------------------------------------------------------------------------
extern "C" void kernel_launch(void* const* d_in, const int* in_sizes, int n_in,
                              void* d_out, int out_size) {
    const float* x     = (const float*)d_in[0];
    const float* freqs = (const float*)d_in[1];
    const float* Wq    = (const float*)d_in[2];
    const float* Wk    = (const float*)d_in[3];
    const float* Wv    = (const float*)d_in[4];
    const float* Wo    = (const float*)d_in[5];
    float* out = (float*)d_out;

    __half *qh = nullptr, *kh = nullptr, *vh = nullptr;
    __half *attnh = nullptr, *xh = nullptr, *wh = nullptr;
    cudaGetSymbolAddress((void**)&qh,    g_qh);
    cudaGetSymbolAddress((void**)&kh,    g_kh);
    cudaGetSymbolAddress((void**)&vh,    g_vh);
    cudaGetSymbolAddress((void**)&attnh, g_attnh);
    cudaGetSymbolAddress((void**)&xh,    g_xh);
    cudaGetSymbolAddress((void**)&wh,    g_wh);

    cudaFuncSetAttribute(gemm_qkv,  cudaFuncAttributeMaxDynamicSharedMemorySize, GH_SMEM_BYTES);
    cudaFuncSetAttribute(gemm_proj, cudaFuncAttributeMaxDynamicSharedMemorySize, GH_SMEM_BYTES);
    cudaFuncSetAttribute(flash_attn_mma, cudaFuncAttributeMaxDynamicSharedMemorySize, HSMEM_BYTES);

    // Fused prepass: x + 4 weight matrices -> half, one launch
    {
        const long long total = (long long)MROWS * CMODEL + 4LL * CMODEL * CMODEL;
        const int blocks = (int)(total / (256 * 8));
        to_half_all<<<blocks, 256>>>(x, Wq, Wk, Wv, Wo, xh, wh);
    }

    gemm_qkv<<<dim3(24, MROWS / 256), 512, GH_SMEM_BYTES>>>(xh, wh, qh, kh, vh, freqs);

    {
        dim3 agrid(SEQ / 128, NHEAD, BATCH);
        flash_attn_mma<<<agrid, 256, HSMEM_BYTES>>>(qh, kh, vh, attnh);
    }

    gemm_proj<<<dim3(CMODEL / 128, MROWS / 256), 512, GH_SMEM_BYTES>>>(attnh, wh, out);
}

// round 14
// speedup vs baseline: 1.9304x; 1.0930x over previous
#include <cuda_runtime.h>
#include <cuda_fp16.h>
#include <cstdint>
#include <math.h>

// Problem constants
#define BATCH 2
#define SEQ   2048
#define CMODEL 1024
#define NHEAD 16
#define HDIM  64
#define MROWS (BATCH * SEQ)   // 4096

// ---------------------------------------------------------------------------
// Scratch
// ---------------------------------------------------------------------------
__device__ __half g_qh[MROWS * CMODEL];
__device__ __half g_kh[MROWS * CMODEL];
__device__ __half g_vh[MROWS * CMODEL];
__device__ __half g_attnh[MROWS * CMODEL];
__device__ __half g_xh[MROWS * CMODEL];
__device__ __half g_wh[4 * CMODEL * CMODEL];   // Wq,Wk,Wv,Wo in half

// ---------------------------------------------------------------------------
// Helpers
// ---------------------------------------------------------------------------
__device__ __forceinline__ uint32_t smem_u32(const void* p) {
    uint32_t a;
    asm("{ .reg .u64 t; cvta.to.shared.u64 t, %1; cvt.u32.u64 %0, t; }" : "=r"(a) : "l"(p));
    return a;
}
__device__ __forceinline__ void cp_async16(uint32_t s, const void* g) {
    asm volatile("cp.async.ca.shared.global [%0], [%1], 16;" :: "r"(s), "l"(g));
}
#define CP_COMMIT()  asm volatile("cp.async.commit_group;" ::: "memory")
#define CP_WAIT(N)   asm volatile("cp.async.wait_group %0;" :: "n"(N) : "memory")

__device__ __forceinline__ void mma_f16(float (&d)[4], const uint32_t (&a)[4],
                                        const uint32_t (&b)[2]) {
    asm volatile(
        "mma.sync.aligned.m16n8k16.row.col.f32.f16.f16.f32 "
        "{%0,%1,%2,%3}, {%4,%5,%6,%7}, {%8,%9}, {%0,%1,%2,%3};"
        : "+f"(d[0]), "+f"(d[1]), "+f"(d[2]), "+f"(d[3])
        : "r"(a[0]), "r"(a[1]), "r"(a[2]), "r"(a[3]), "r"(b[0]), "r"(b[1]));
}
__device__ __forceinline__ void ldsm_x2_trans(uint32_t& r0, uint32_t& r1, uint32_t addr) {
    asm volatile("ldmatrix.sync.aligned.m8n8.x2.trans.shared.b16 {%0,%1}, [%2];"
                 : "=r"(r0), "=r"(r1) : "r"(addr));
}

// ---------------------------------------------------------------------------
// Fused prepass: fp32 -> fp16 for x + all four weight matrices, one launch.
// ---------------------------------------------------------------------------
__global__ void to_half_all(const float* __restrict__ x,
                            const float* __restrict__ wq,
                            const float* __restrict__ wk,
                            const float* __restrict__ wv,
                            const float* __restrict__ wo,
                            __half* __restrict__ xh,
                            __half* __restrict__ wh) {
    const long long nx = (long long)MROWS * CMODEL;     // 4M
    const long long nw = (long long)CMODEL * CMODEL;    // 1M
    long long i = (long long)(blockIdx.x * 256 + threadIdx.x) * 8;
    if (i >= nx + 4 * nw) return;

    const float* src;
    __half* dst;
    long long off;
    if (i < nx) {
        src = x; dst = xh; off = i;
    } else {
        long long j = i - nx;
        int s = (int)(j / nw);
        off = j - (long long)s * nw;
        src = (s == 0) ? wq : (s == 1) ? wk : (s == 2) ? wv : wo;
        dst = wh + (size_t)s * nw;
    }
    float4 v0 = *reinterpret_cast<const float4*>(src + off);
    float4 v1 = *reinterpret_cast<const float4*>(src + off + 4);
    __half2 h[4];
    h[0] = __floats2half2_rn(v0.x, v0.y);
    h[1] = __floats2half2_rn(v0.z, v0.w);
    h[2] = __floats2half2_rn(v1.x, v1.y);
    h[3] = __floats2half2_rn(v1.z, v1.w);
    *reinterpret_cast<uint2*>(dst + off)     = *reinterpret_cast<uint2*>(&h[0]);
    *reinterpret_cast<uint2*>(dst + off + 4) = *reinterpret_cast<uint2*>(&h[2]);
}

// ---------------------------------------------------------------------------
// FP16 mma.sync GEMM body: C = A * W^T, fp32 accum. 3-stage cp.async pipeline.
// CTA tile 128x128, 256 threads = 8 warps in 2(M) x 4(N); warp tile 64x32.
// 2 CTAs/SM for barrier overlap.
// ---------------------------------------------------------------------------
#define BK 32
#define KSTH 40
#define ATH (128 * KSTH)
#define WTH (128 * KSTH)
#define STAGEH (ATH + WTH)
#define GH_SMEM_BYTES (3 * STAGEH * 2)   // 61440

__device__ __forceinline__ void gemm_body_h(const __half* __restrict__ A,
                                            const __half* __restrict__ W,
                                            float* __restrict__ Cf,
                                            __half* __restrict__ Ch,
                                            const float* __restrict__ freqs,
                                            int m0, int n0, bool rope,
                                            __half* smem) {
    const int K = CMODEL, N = CMODEL;
    __half* As[3] = { smem, smem + STAGEH, smem + 2 * STAGEH };
    __half* Ws[3] = { smem + ATH, smem + STAGEH + ATH, smem + 2 * STAGEH + ATH };

    const int tid  = threadIdx.x;
    const int lane = tid & 31;
    const int wid  = tid >> 5;       // 0..7
    const int g    = lane >> 2;
    const int tg   = lane & 3;
    const int wm   = (wid & 1) * 64;     // 2 M-groups
    const int wn   = (wid >> 1) * 32;    // 4 N-groups

    float acc[4][4][4];
#pragma unroll
    for (int mt = 0; mt < 4; mt++)
#pragma unroll
        for (int nt = 0; nt < 4; nt++)
#pragma unroll
            for (int r = 0; r < 4; r++) acc[mt][nt][r] = 0.0f;

    const int ntiles = K / BK;   // 32

    // loaders (256 threads): A tile 512 16B-chunks (2/thread), W same
    auto load_tile = [&](int kt, int stg) {
        const int ko = kt * BK;
#pragma unroll
        for (int i = 0; i < 2; i++) {
            const int f = tid + 256 * i;       // 0..511
            const int row = f >> 2;            // 0..127
            const int c8 = (f & 3) * 8;
            cp_async16(smem_u32(&As[stg][row * KSTH + c8]),
                       &A[(size_t)(m0 + row) * K + ko + c8]);
            cp_async16(smem_u32(&Ws[stg][row * KSTH + c8]),
                       &W[(size_t)(n0 + row) * K + ko + c8]);
        }
    };

    load_tile(0, 0);
    CP_COMMIT();
    load_tile(1, 1);
    CP_COMMIT();

    for (int kt = 0; kt < ntiles; kt++) {
        if (kt + 2 < ntiles) {
            load_tile(kt + 2, (kt + 2) % 3);
            CP_COMMIT();
            CP_WAIT(2);
        } else if (kt + 1 < ntiles) {
            CP_WAIT(1);
        } else {
            CP_WAIT(0);
        }
        __syncthreads();

        const __half* at = As[kt % 3];
        const __half* wt = Ws[kt % 3];
#pragma unroll
        for (int ks = 0; ks < 2; ks++) {
            const int kc = ks * 16 + 2 * tg;
            uint32_t a[4][4];
#pragma unroll
            for (int mt = 0; mt < 4; mt++) {
                const int r0 = (wm + mt * 16 + g) * KSTH;
                a[mt][0] = *reinterpret_cast<const uint32_t*>(at + r0 + kc);
                a[mt][1] = *reinterpret_cast<const uint32_t*>(at + r0 + 8 * KSTH + kc);
                a[mt][2] = *reinterpret_cast<const uint32_t*>(at + r0 + kc + 8);
                a[mt][3] = *reinterpret_cast<const uint32_t*>(at + r0 + 8 * KSTH + kc + 8);
            }
            uint32_t b[4][2];
#pragma unroll
            for (int nt = 0; nt < 4; nt++) {
                const int r0 = (wn + nt * 8 + g) * KSTH;
                b[nt][0] = *reinterpret_cast<const uint32_t*>(wt + r0 + kc);
                b[nt][1] = *reinterpret_cast<const uint32_t*>(wt + r0 + kc + 8);
            }
#pragma unroll
            for (int mt = 0; mt < 4; mt++)
#pragma unroll
                for (int nt = 0; nt < 4; nt++)
                    mma_f16(acc[mt][nt], a[mt], b[nt]);
        }
        __syncthreads();
    }

    // epilogue: optional fused RoPE; half or float output
#pragma unroll
    for (int mt = 0; mt < 4; mt++) {
        const int row = m0 + wm + mt * 16 + g;
        const int t0 = row & (SEQ - 1);
        const int t1 = (row + 8) & (SEQ - 1);
#pragma unroll
        for (int nt = 0; nt < 4; nt++) {
            const int col = n0 + wn + nt * 8 + 2 * tg;
            float2 v0 = make_float2(acc[mt][nt][0], acc[mt][nt][1]);
            float2 v1 = make_float2(acc[mt][nt][2], acc[mt][nt][3]);
            if (rope) {
                const int fo = (col & 62);
                float cc0 = freqs[t0 * HDIM + fo], ss0 = freqs[t0 * HDIM + fo + 1];
                float cc1 = freqs[t1 * HDIM + fo], ss1 = freqs[t1 * HDIM + fo + 1];
                v0 = make_float2(v0.x * cc0 - v0.y * ss0, v0.x * ss0 + v0.y * cc0);
                v1 = make_float2(v1.x * cc1 - v1.y * ss1, v1.x * ss1 + v1.y * cc1);
            }
            if (Ch) {
                *reinterpret_cast<__half2*>(&Ch[(size_t)row * N + col]) =
                    __floats2half2_rn(v0.x, v0.y);
                *reinterpret_cast<__half2*>(&Ch[(size_t)(row + 8) * N + col]) =
                    __floats2half2_rn(v1.x, v1.y);
            } else {
                *reinterpret_cast<float2*>(&Cf[(size_t)row * N + col]) = v0;
                *reinterpret_cast<float2*>(&Cf[(size_t)(row + 8) * N + col]) = v1;
            }
        }
    }
}

// Fused QKV + RoPE, half outputs. grid.x: 0..23 = (matrix, n-block)
__global__ __launch_bounds__(256, 2) void gemm_qkv(const __half* __restrict__ xh,
                                                   const __half* __restrict__ wh,
                                                   __half* __restrict__ q,
                                                   __half* __restrict__ k,
                                                   __half* __restrict__ v,
                                                   const float* __restrict__ freqs) {
    extern __shared__ __half smemh[];
    const int wsel = blockIdx.x >> 3;
    const int n0 = (blockIdx.x & 7) * 128;
    const int m0 = blockIdx.y * 128;
    const __half* W = wh + (size_t)wsel * CMODEL * CMODEL;
    __half* C = (wsel == 0) ? q : (wsel == 1) ? k : v;
    gemm_body_h(xh, W, nullptr, C, freqs, m0, n0, wsel < 2, smemh);
}

__global__ __launch_bounds__(256, 2) void gemm_proj(const __half* __restrict__ attnh,
                                                    const __half* __restrict__ wh,
                                                    float* __restrict__ C) {
    extern __shared__ __half smemh[];
    gemm_body_h(attnh, wh + (size_t)3 * CMODEL * CMODEL, C, nullptr, nullptr,
                blockIdx.y * 128, blockIdx.x * 128, false, smemh);
}

// ---------------------------------------------------------------------------
// FP16 tensor-core flash-attention, causal. 3-stage cp.async pipeline.
// CTA: 128 queries x 1 head, 8 warps x 16 rows, 64-key tiles, 2 CTAs/SM.
// ---------------------------------------------------------------------------
#define VROW 72                          // halves per SMEM row
#define HTILE (64 * VROW)                // halves per K or V tile (4608)
#define HSMEM_BYTES (6 * HTILE * 2 + 128 * VROW * 2)   // 55296 + 18432 = 73728

__global__ __launch_bounds__(256, 2) void flash_attn_mma(const __half* __restrict__ Q,
                                                         const __half* __restrict__ K,
                                                         const __half* __restrict__ V,
                                                         __half* __restrict__ O) {
    extern __shared__ __half smh[];
    __half* Ksm[3] = { smh, smh + 2 * HTILE, smh + 4 * HTILE };
    __half* Ps = smh + 6 * HTILE;        // [128][VROW]

    const int tid  = threadIdx.x;
    const int lane = tid & 31;
    const int wid  = tid >> 5;
    const int g    = lane >> 2;
    const int tg   = lane & 3;

    const int qb = (int)gridDim.x - 1 - (int)blockIdx.x;
    const int h  = blockIdx.y;
    const int b  = blockIdx.z;
    const int q0 = qb * 128;
    const int wrow = wid * 16;
    const int r0g = q0 + wrow + g;
    const int r1g = r0g + 8;

    // Q fragments: half2 pairs, pre-scaled by 0.125 (pow2, exact)
    const __half2 s2 = __half2half2(__float2half(0.125f));
    uint32_t qf[4][4];
    {
        const __half* q0p = Q + (((size_t)b * SEQ + r0g) * NHEAD + h) * HDIM;
        const __half* q1p = Q + (((size_t)b * SEQ + r1g) * NHEAD + h) * HDIM;
#pragma unroll
        for (int ks = 0; ks < 4; ks++) {
            const int kc = ks * 16 + 2 * tg;
            __half2 h0 = __hmul2(*reinterpret_cast<const __half2*>(q0p + kc), s2);
            __half2 h1 = __hmul2(*reinterpret_cast<const __half2*>(q1p + kc), s2);
            __half2 h2 = __hmul2(*reinterpret_cast<const __half2*>(q0p + kc + 8), s2);
            __half2 h3 = __hmul2(*reinterpret_cast<const __half2*>(q1p + kc + 8), s2);
            qf[ks][0] = *reinterpret_cast<uint32_t*>(&h0);
            qf[ks][1] = *reinterpret_cast<uint32_t*>(&h1);
            qf[ks][2] = *reinterpret_cast<uint32_t*>(&h2);
            qf[ks][3] = *reinterpret_cast<uint32_t*>(&h3);
        }
    }

    float of[8][4];
#pragma unroll
    for (int nt = 0; nt < 8; nt++)
#pragma unroll
        for (int r = 0; r < 4; r++) of[nt][r] = 0.0f;
    float mrow[2] = { -1e30f, -1e30f };
    float lrow[2] = { 0.0f, 0.0f };

    const int ntiles = (q0 + 128) / 64;

    const uint32_t ks0 = smem_u32(Ksm[0]);
    const uint32_t stageB = 2 * HTILE * 2;   // bytes between stages (K+V pair)

    auto prefetch = [&](int t, int s) {
        const int kt = t * 64;
#pragma unroll
        for (int i = 0; i < 2; i++) {
            const int f = tid + 256 * i;       // 0..511
            const int row = f >> 3;            // 0..63
            const int c8 = (f & 7) * 8;        // half offset
            const size_t gsrc = (((size_t)b * SEQ + kt + row) * NHEAD + h) * HDIM + c8;
            const uint32_t soff = s * stageB + (row * VROW + c8) * 2;
            cp_async16(ks0 + soff, &K[gsrc]);
            cp_async16(ks0 + soff + HTILE * 2, &V[gsrc]);
        }
    };

    prefetch(0, 0);
    CP_COMMIT();
    if (ntiles > 1) { prefetch(1, 1); CP_COMMIT(); }

    for (int t = 0; t < ntiles; t++) {
        const int kt = t * 64;
        if (t + 2 < ntiles) {
            prefetch(t + 2, (t + 2) % 3);
            CP_COMMIT();
            CP_WAIT(2);
        } else if (t + 1 < ntiles) {
            CP_WAIT(1);
        } else {
            CP_WAIT(0);
        }
        __syncthreads();

        const bool skip = kt > q0 + wrow + 15;
        if (!skip) {
            const __half* kb = Ksm[t % 3];
            const uint32_t vbase = ks0 + (t % 3) * stageB + HTILE * 2;

            // ---- S = Q * K^T ----
            float sacc[8][4];
#pragma unroll
            for (int nt = 0; nt < 8; nt++)
#pragma unroll
                for (int r = 0; r < 4; r++) sacc[nt][r] = 0.0f;

#pragma unroll
            for (int ks = 0; ks < 4; ks++) {
                const int kc = ks * 16 + 2 * tg;
#pragma unroll
                for (int nt = 0; nt < 8; nt++) {
                    const __half* kr = kb + (nt * 8 + g) * VROW + kc;
                    uint32_t bf[2];
                    bf[0] = *reinterpret_cast<const uint32_t*>(kr);
                    bf[1] = *reinterpret_cast<const uint32_t*>(kr + 8);
                    mma_f16(sacc[nt], qf[ks], bf);
                }
            }

            // ---- causal mask ----
            if (kt + 63 > q0 + wrow) {
#pragma unroll
                for (int nt = 0; nt < 8; nt++) {
                    const int c = kt + nt * 8 + 2 * tg;
                    if (c > r0g)     sacc[nt][0] = -1e30f;
                    if (c + 1 > r0g) sacc[nt][1] = -1e30f;
                    if (c > r1g)     sacc[nt][2] = -1e30f;
                    if (c + 1 > r1g) sacc[nt][3] = -1e30f;
                }
            }

            // ---- online softmax (fp32) ----
            float rmax0 = -1e30f, rmax1 = -1e30f;
#pragma unroll
            for (int nt = 0; nt < 8; nt++) {
                rmax0 = fmaxf(rmax0, fmaxf(sacc[nt][0], sacc[nt][1]));
                rmax1 = fmaxf(rmax1, fmaxf(sacc[nt][2], sacc[nt][3]));
            }
            rmax0 = fmaxf(rmax0, __shfl_xor_sync(0xffffffff, rmax0, 1));
            rmax0 = fmaxf(rmax0, __shfl_xor_sync(0xffffffff, rmax0, 2));
            rmax1 = fmaxf(rmax1, __shfl_xor_sync(0xffffffff, rmax1, 1));
            rmax1 = fmaxf(rmax1, __shfl_xor_sync(0xffffffff, rmax1, 2));

            const float mn0 = fmaxf(mrow[0], rmax0);
            const float mn1 = fmaxf(mrow[1], rmax1);
            const float corr0 = __expf(mrow[0] - mn0);
            const float corr1 = __expf(mrow[1] - mn1);
            mrow[0] = mn0; mrow[1] = mn1;

            float rs0 = 0.0f, rs1 = 0.0f;
            __half* p0row = Ps + (wrow + g) * VROW + 2 * tg;
            __half* p1row = Ps + (wrow + g + 8) * VROW + 2 * tg;
#pragma unroll
            for (int nt = 0; nt < 8; nt++) {
                const float e0 = __expf(sacc[nt][0] - mn0);
                const float e1 = __expf(sacc[nt][1] - mn0);
                const float e2 = __expf(sacc[nt][2] - mn1);
                const float e3 = __expf(sacc[nt][3] - mn1);
                rs0 += e0 + e1;
                rs1 += e2 + e3;
                *reinterpret_cast<__half2*>(p0row + nt * 8) = __floats2half2_rn(e0, e1);
                *reinterpret_cast<__half2*>(p1row + nt * 8) = __floats2half2_rn(e2, e3);
            }
            rs0 += __shfl_xor_sync(0xffffffff, rs0, 1);
            rs0 += __shfl_xor_sync(0xffffffff, rs0, 2);
            rs1 += __shfl_xor_sync(0xffffffff, rs1, 1);
            rs1 += __shfl_xor_sync(0xffffffff, rs1, 2);
            lrow[0] = lrow[0] * corr0 + rs0;
            lrow[1] = lrow[1] * corr1 + rs1;

#pragma unroll
            for (int nt = 0; nt < 8; nt++) {
                of[nt][0] *= corr0; of[nt][1] *= corr0;
                of[nt][2] *= corr1; of[nt][3] *= corr1;
            }
            __syncwarp();

            // ---- O += P * V (V via ldmatrix.trans) ----
#pragma unroll
            for (int ks = 0; ks < 4; ks++) {
                const int kc = ks * 16 + 2 * tg;
                uint32_t a[4];
                a[0] = *reinterpret_cast<const uint32_t*>(Ps + (wrow + g) * VROW + kc);
                a[1] = *reinterpret_cast<const uint32_t*>(Ps + (wrow + g + 8) * VROW + kc);
                a[2] = *reinterpret_cast<const uint32_t*>(Ps + (wrow + g) * VROW + kc + 8);
                a[3] = *reinterpret_cast<const uint32_t*>(Ps + (wrow + g + 8) * VROW + kc + 8);
                const uint32_t lrowaddr = vbase + ((ks * 16 + (lane & 15)) * VROW) * 2;
#pragma unroll
                for (int nt = 0; nt < 8; nt++) {
                    uint32_t bf[2];
                    ldsm_x2_trans(bf[0], bf[1], lrowaddr + nt * 16);
                    mma_f16(of[nt], a, bf);
                }
            }
        }
        __syncthreads();
    }

    // ---- epilogue: half2 coalesced output ----
    const float inv0 = 1.0f / lrow[0];
    const float inv1 = 1.0f / lrow[1];
    __half* o0 = O + (((size_t)b * SEQ + r0g) * NHEAD + h) * HDIM;
    __half* o1 = O + (((size_t)b * SEQ + r1g) * NHEAD + h) * HDIM;
#pragma unroll
    for (int nt = 0; nt < 8; nt++) {
        const int col = nt * 8 + 2 * tg;
        *reinterpret_cast<__half2*>(o0 + col) =
            __floats2half2_rn(of[nt][0] * inv0, of[nt][1] * inv0);
        *reinterpret_cast<__half2*>(o1 + col) =
            __floats2half2_rn(of[nt][2] * inv1, of[nt][3] * inv1);
    }
}

// ---------------------------------------------------------------------------
// kernel_launch
// ---------------------------------------------------------------------------
extern "C" void kernel_launch(void* const* d_in, const int* in_sizes, int n_in,
                              void* d_out, int out_size) {
    const float* x     = (const float*)d_in[0];
    const float* freqs = (const float*)d_in[1];
    const float* Wq    = (const float*)d_in[2];
    const float* Wk    = (const float*)d_in[3];
    const float* Wv    = (const float*)d_in[4];
    const float* Wo    = (const float*)d_in[5];
    float* out = (float*)d_out;

    __half *qh = nullptr, *kh = nullptr, *vh = nullptr;
    __half *attnh = nullptr, *xh = nullptr, *wh = nullptr;
    cudaGetSymbolAddress((void**)&qh,    g_qh);
    cudaGetSymbolAddress((void**)&kh,    g_kh);
    cudaGetSymbolAddress((void**)&vh,    g_vh);
    cudaGetSymbolAddress((void**)&attnh, g_attnh);
    cudaGetSymbolAddress((void**)&xh,    g_xh);
    cudaGetSymbolAddress((void**)&wh,    g_wh);

    cudaFuncSetAttribute(gemm_qkv,  cudaFuncAttributeMaxDynamicSharedMemorySize, GH_SMEM_BYTES);
    cudaFuncSetAttribute(gemm_proj, cudaFuncAttributeMaxDynamicSharedMemorySize, GH_SMEM_BYTES);
    cudaFuncSetAttribute(flash_attn_mma, cudaFuncAttributeMaxDynamicSharedMemorySize, HSMEM_BYTES);

    // Fused prepass: x + 4 weight matrices -> half, one launch
    {
        const long long total = (long long)MROWS * CMODEL + 4LL * CMODEL * CMODEL;
        const int blocks = (int)(total / (256 * 8));
        to_half_all<<<blocks, 256>>>(x, Wq, Wk, Wv, Wo, xh, wh);
    }

    gemm_qkv<<<dim3(24, MROWS / 128), 256, GH_SMEM_BYTES>>>(xh, wh, qh, kh, vh, freqs);

    {
        dim3 agrid(SEQ / 128, NHEAD, BATCH);
        flash_attn_mma<<<agrid, 256, HSMEM_BYTES>>>(qh, kh, vh, attnh);
    }

    gemm_proj<<<dim3(CMODEL / 128, MROWS / 128), 256, GH_SMEM_BYTES>>>(attnh, wh, out);
}

// round 15
// speedup vs baseline: 2.3209x; 1.2023x over previous
#include <cuda_runtime.h>
#include <cuda_fp16.h>
#include <cstdint>
#include <math.h>

// Problem constants
#define BATCH 2
#define SEQ   2048
#define CMODEL 1024
#define NHEAD 16
#define HDIM  64
#define MROWS (BATCH * SEQ)   // 4096

// ---------------------------------------------------------------------------
// Scratch
// ---------------------------------------------------------------------------
__device__ __half g_qh[MROWS * CMODEL];
__device__ __half g_kh[MROWS * CMODEL];
__device__ __half g_vh[MROWS * CMODEL];
__device__ __half g_attnh[MROWS * CMODEL];
__device__ __half g_xh[MROWS * CMODEL];
__device__ __half g_wh[4 * CMODEL * CMODEL];

// ---------------------------------------------------------------------------
// Helpers
// ---------------------------------------------------------------------------
__device__ __forceinline__ uint32_t smem_u32(const void* p) {
    uint32_t a;
    asm("{ .reg .u64 t; cvta.to.shared.u64 t, %1; cvt.u32.u64 %0, t; }" : "=r"(a) : "l"(p));
    return a;
}
__device__ __forceinline__ void cp_async16(uint32_t s, const void* g) {
    asm volatile("cp.async.ca.shared.global [%0], [%1], 16;" :: "r"(s), "l"(g));
}
#define CP_COMMIT()  asm volatile("cp.async.commit_group;" ::: "memory")
#define CP_WAIT(N)   asm volatile("cp.async.wait_group %0;" :: "n"(N) : "memory")

__device__ __forceinline__ void mma_f16(float (&d)[4], const uint32_t (&a)[4],
                                        const uint32_t (&b)[2]) {
    asm volatile(
        "mma.sync.aligned.m16n8k16.row.col.f32.f16.f16.f32 "
        "{%0,%1,%2,%3}, {%4,%5,%6,%7}, {%8,%9}, {%0,%1,%2,%3};"
        : "+f"(d[0]), "+f"(d[1]), "+f"(d[2]), "+f"(d[3])
        : "r"(a[0]), "r"(a[1]), "r"(a[2]), "r"(a[3]), "r"(b[0]), "r"(b[1]));
}
__device__ __forceinline__ void ldsm_x4(uint32_t& r0, uint32_t& r1, uint32_t& r2,
                                        uint32_t& r3, uint32_t addr) {
    asm volatile("ldmatrix.sync.aligned.m8n8.x4.shared.b16 {%0,%1,%2,%3}, [%4];"
                 : "=r"(r0), "=r"(r1), "=r"(r2), "=r"(r3) : "r"(addr));
}
__device__ __forceinline__ void ldsm_x2_trans(uint32_t& r0, uint32_t& r1, uint32_t addr) {
    asm volatile("ldmatrix.sync.aligned.m8n8.x2.trans.shared.b16 {%0,%1}, [%2];"
                 : "=r"(r0), "=r"(r1) : "r"(addr));
}

// ---------------------------------------------------------------------------
// Fused prepass: fp32 -> fp16, one launch
// ---------------------------------------------------------------------------
__global__ void to_half_all(const float* __restrict__ x,
                            const float* __restrict__ wq,
                            const float* __restrict__ wk,
                            const float* __restrict__ wv,
                            const float* __restrict__ wo,
                            __half* __restrict__ xh,
                            __half* __restrict__ wh) {
    const long long nx = (long long)MROWS * CMODEL;
    const long long nw = (long long)CMODEL * CMODEL;
    long long i = (long long)(blockIdx.x * 256 + threadIdx.x) * 8;
    if (i >= nx + 4 * nw) return;

    const float* src;
    __half* dst;
    long long off;
    if (i < nx) {
        src = x; dst = xh; off = i;
    } else {
        long long j = i - nx;
        int s = (int)(j / nw);
        off = j - (long long)s * nw;
        src = (s == 0) ? wq : (s == 1) ? wk : (s == 2) ? wv : wo;
        dst = wh + (size_t)s * nw;
    }
    float4 v0 = *reinterpret_cast<const float4*>(src + off);
    float4 v1 = *reinterpret_cast<const float4*>(src + off + 4);
    __half2 h[4];
    h[0] = __floats2half2_rn(v0.x, v0.y);
    h[1] = __floats2half2_rn(v0.z, v0.w);
    h[2] = __floats2half2_rn(v1.x, v1.y);
    h[3] = __floats2half2_rn(v1.z, v1.w);
    *reinterpret_cast<uint2*>(dst + off)     = *reinterpret_cast<uint2*>(&h[0]);
    *reinterpret_cast<uint2*>(dst + off + 4) = *reinterpret_cast<uint2*>(&h[2]);
}

// ---------------------------------------------------------------------------
// FP16 GEMM: C = A * W^T. CTA 128x128, 256 threads, warp tile 64x32,
// 3-stage pipeline, ldmatrix fragments, one barrier/tile, 2 CTAs/SM.
// ---------------------------------------------------------------------------
#define BK 32
#define KSTH 40
#define ATH (128 * KSTH)
#define WTH (128 * KSTH)
#define STAGEH (ATH + WTH)
#define GH_SMEM_BYTES (3 * STAGEH * 2)   // 61440

__device__ __forceinline__ void gemm_body_h(const __half* __restrict__ A,
                                            const __half* __restrict__ W,
                                            float* __restrict__ Cf,
                                            __half* __restrict__ Ch,
                                            const float* __restrict__ freqs,
                                            int m0, int n0, bool rope,
                                            __half* smem) {
    const int K = CMODEL, N = CMODEL;
    __half* As[3] = { smem, smem + STAGEH, smem + 2 * STAGEH };
    __half* Ws[3] = { smem + ATH, smem + STAGEH + ATH, smem + 2 * STAGEH + ATH };

    const int tid  = threadIdx.x;
    const int lane = tid & 31;
    const int wid  = tid >> 5;       // 0..7
    const int g    = lane >> 2;
    const int tg   = lane & 3;
    const int wm   = (wid & 1) * 64;
    const int wn   = (wid >> 1) * 32;

    // ldmatrix lane mappings (byte offsets within a stage)
    const int arow = (lane & 7) + ((lane >> 3) & 1) * 8;   // A-type x4
    const int acol = (lane >> 4) * 8;                       // halves
    const int brow = (lane & 7) + ((lane >> 4) & 1) * 8;   // B-type x4 (nt pair)
    const int bcol = ((lane >> 3) & 1) * 8;

    uint32_t aoff[4], boff[2];
#pragma unroll
    for (int mt = 0; mt < 4; mt++)
        aoff[mt] = ((wm + mt * 16 + arow) * KSTH + acol) * 2;
#pragma unroll
    for (int j = 0; j < 2; j++)
        boff[j] = (ATH + (wn + j * 16 + brow) * KSTH + bcol) * 2;

    float acc[4][4][4];
#pragma unroll
    for (int mt = 0; mt < 4; mt++)
#pragma unroll
        for (int nt = 0; nt < 4; nt++)
#pragma unroll
            for (int r = 0; r < 4; r++) acc[mt][nt][r] = 0.0f;

    const int ntiles = K / BK;   // 32

    auto load_tile = [&](int kt, int stg) {
        const int ko = kt * BK;
#pragma unroll
        for (int i = 0; i < 2; i++) {
            const int f = tid + 256 * i;
            const int row = f >> 2;
            const int c8 = (f & 3) * 8;
            cp_async16(smem_u32(&As[stg][row * KSTH + c8]),
                       &A[(size_t)(m0 + row) * K + ko + c8]);
            cp_async16(smem_u32(&Ws[stg][row * KSTH + c8]),
                       &W[(size_t)(n0 + row) * K + ko + c8]);
        }
    };

    load_tile(0, 0);
    CP_COMMIT();
    load_tile(1, 1);
    CP_COMMIT();

    const uint32_t sbase = smem_u32(smem);

    for (int kt = 0; kt < ntiles; kt++) {
        if (kt + 1 < ntiles) { CP_WAIT(1); } else { CP_WAIT(0); }
        __syncthreads();
        if (kt + 2 < ntiles) {
            load_tile(kt + 2, (kt + 2) % 3);
            CP_COMMIT();
        }

        const uint32_t stg = sbase + (uint32_t)((kt % 3) * STAGEH * 2);
#pragma unroll
        for (int ks = 0; ks < 2; ks++) {
            const uint32_t kb = (uint32_t)(ks * 32);   // 16 halves = 32 bytes
            uint32_t a[4][4];
#pragma unroll
            for (int mt = 0; mt < 4; mt++)
                ldsm_x4(a[mt][0], a[mt][1], a[mt][2], a[mt][3], stg + aoff[mt] + kb);
            uint32_t b[4][2];
#pragma unroll
            for (int j = 0; j < 2; j++)
                ldsm_x4(b[2 * j][0], b[2 * j][1], b[2 * j + 1][0], b[2 * j + 1][1],
                        stg + boff[j] + kb);
#pragma unroll
            for (int mt = 0; mt < 4; mt++)
#pragma unroll
                for (int nt = 0; nt < 4; nt++)
                    mma_f16(acc[mt][nt], a[mt], b[nt]);
        }
        __syncthreads();
    }

    // epilogue
#pragma unroll
    for (int mt = 0; mt < 4; mt++) {
        const int row = m0 + wm + mt * 16 + g;
        const int t0 = row & (SEQ - 1);
        const int t1 = (row + 8) & (SEQ - 1);
#pragma unroll
        for (int nt = 0; nt < 4; nt++) {
            const int col = n0 + wn + nt * 8 + 2 * tg;
            float2 v0 = make_float2(acc[mt][nt][0], acc[mt][nt][1]);
            float2 v1 = make_float2(acc[mt][nt][2], acc[mt][nt][3]);
            if (rope) {
                const int fo = (col & 62);
                float cc0 = freqs[t0 * HDIM + fo], ss0 = freqs[t0 * HDIM + fo + 1];
                float cc1 = freqs[t1 * HDIM + fo], ss1 = freqs[t1 * HDIM + fo + 1];
                v0 = make_float2(v0.x * cc0 - v0.y * ss0, v0.x * ss0 + v0.y * cc0);
                v1 = make_float2(v1.x * cc1 - v1.y * ss1, v1.x * ss1 + v1.y * cc1);
            }
            if (Ch) {
                *reinterpret_cast<__half2*>(&Ch[(size_t)row * N + col]) =
                    __floats2half2_rn(v0.x, v0.y);
                *reinterpret_cast<__half2*>(&Ch[(size_t)(row + 8) * N + col]) =
                    __floats2half2_rn(v1.x, v1.y);
            } else {
                *reinterpret_cast<float2*>(&Cf[(size_t)row * N + col]) = v0;
                *reinterpret_cast<float2*>(&Cf[(size_t)(row + 8) * N + col]) = v1;
            }
        }
    }
}

__global__ __launch_bounds__(256, 2) void gemm_qkv(const __half* __restrict__ xh,
                                                   const __half* __restrict__ wh,
                                                   __half* __restrict__ q,
                                                   __half* __restrict__ k,
                                                   __half* __restrict__ v,
                                                   const float* __restrict__ freqs) {
    extern __shared__ __half smemh[];
    const int wsel = blockIdx.x >> 3;
    const int n0 = (blockIdx.x & 7) * 128;
    const int m0 = blockIdx.y * 128;
    const __half* W = wh + (size_t)wsel * CMODEL * CMODEL;
    __half* C = (wsel == 0) ? q : (wsel == 1) ? k : v;
    gemm_body_h(xh, W, nullptr, C, freqs, m0, n0, wsel < 2, smemh);
}

__global__ __launch_bounds__(256, 2) void gemm_proj(const __half* __restrict__ attnh,
                                                    const __half* __restrict__ wh,
                                                    float* __restrict__ C) {
    extern __shared__ __half smemh[];
    gemm_body_h(attnh, wh + (size_t)3 * CMODEL * CMODEL, C, nullptr, nullptr,
                blockIdx.y * 128, blockIdx.x * 128, false, smemh);
}

// ---------------------------------------------------------------------------
// FP16 flash-attention, causal. 3-stage pipeline, ldmatrix fragments,
// one barrier/tile, 2 CTAs/SM.
// ---------------------------------------------------------------------------
#define VROW 72
#define HTILE (64 * VROW)
#define HSMEM_BYTES (6 * HTILE * 2 + 128 * VROW * 2)   // 73728

__global__ __launch_bounds__(256, 2) void flash_attn_mma(const __half* __restrict__ Q,
                                                         const __half* __restrict__ K,
                                                         const __half* __restrict__ V,
                                                         __half* __restrict__ O) {
    extern __shared__ __half smh[];
    __half* Ps = smh + 6 * HTILE;        // [128][VROW]

    const int tid  = threadIdx.x;
    const int lane = tid & 31;
    const int wid  = tid >> 5;
    const int g    = lane >> 2;
    const int tg   = lane & 3;

    const int qb = (int)gridDim.x - 1 - (int)blockIdx.x;
    const int h  = blockIdx.y;
    const int b  = blockIdx.z;
    const int q0 = qb * 128;
    const int wrow = wid * 16;
    const int r0g = q0 + wrow + g;
    const int r1g = r0g + 8;

    // ldmatrix lane mappings
    const int arow = (lane & 7) + ((lane >> 3) & 1) * 8;   // A-type x4
    const int acol = (lane >> 4) * 8;
    const int brow = (lane & 7) + ((lane >> 4) & 1) * 8;   // B-type x4 (nt pair)
    const int bcol = ((lane >> 3) & 1) * 8;

    // Q fragments: half2 pairs, pre-scaled by 0.125 (pow2, exact)
    const __half2 s2 = __half2half2(__float2half(0.125f));
    uint32_t qf[4][4];
    {
        const __half* q0p = Q + (((size_t)b * SEQ + r0g) * NHEAD + h) * HDIM;
        const __half* q1p = Q + (((size_t)b * SEQ + r1g) * NHEAD + h) * HDIM;
#pragma unroll
        for (int ks = 0; ks < 4; ks++) {
            const int kc = ks * 16 + 2 * tg;
            __half2 h0 = __hmul2(*reinterpret_cast<const __half2*>(q0p + kc), s2);
            __half2 h1 = __hmul2(*reinterpret_cast<const __half2*>(q1p + kc), s2);
            __half2 h2 = __hmul2(*reinterpret_cast<const __half2*>(q0p + kc + 8), s2);
            __half2 h3 = __hmul2(*reinterpret_cast<const __half2*>(q1p + kc + 8), s2);
            qf[ks][0] = *reinterpret_cast<uint32_t*>(&h0);
            qf[ks][1] = *reinterpret_cast<uint32_t*>(&h1);
            qf[ks][2] = *reinterpret_cast<uint32_t*>(&h2);
            qf[ks][3] = *reinterpret_cast<uint32_t*>(&h3);
        }
    }

    float of[8][4];
#pragma unroll
    for (int nt = 0; nt < 8; nt++)
#pragma unroll
        for (int r = 0; r < 4; r++) of[nt][r] = 0.0f;
    float mrow[2] = { -1e30f, -1e30f };
    float lrow[2] = { 0.0f, 0.0f };

    const int ntiles = (q0 + 128) / 64;

    const uint32_t ks0 = smem_u32(smh);
    const uint32_t stageB = 2 * HTILE * 2;
    const uint32_t psbase = smem_u32(Ps);

    auto prefetch = [&](int t, int s) {
        const int kt = t * 64;
#pragma unroll
        for (int i = 0; i < 2; i++) {
            const int f = tid + 256 * i;
            const int row = f >> 3;
            const int c8 = (f & 7) * 8;
            const size_t gsrc = (((size_t)b * SEQ + kt + row) * NHEAD + h) * HDIM + c8;
            const uint32_t soff = s * stageB + (row * VROW + c8) * 2;
            cp_async16(ks0 + soff, &K[gsrc]);
            cp_async16(ks0 + soff + HTILE * 2, &V[gsrc]);
        }
    };

    prefetch(0, 0);
    CP_COMMIT();
    prefetch(1, 1);
    CP_COMMIT();

    for (int t = 0; t < ntiles; t++) {
        const int kt = t * 64;
        if (t + 1 < ntiles) { CP_WAIT(1); } else { CP_WAIT(0); }
        __syncthreads();
        if (t + 2 < ntiles) {
            prefetch(t + 2, (t + 2) % 3);
            CP_COMMIT();
        }

        const bool skip = kt > q0 + wrow + 15;
        if (!skip) {
            const uint32_t kbase = ks0 + (t % 3) * stageB;
            const uint32_t vbase = kbase + HTILE * 2;

            // ---- S = Q * K^T; K fragments via ldmatrix.x4 over nt pairs ----
            float sacc[8][4];
#pragma unroll
            for (int nt = 0; nt < 8; nt++)
#pragma unroll
                for (int r = 0; r < 4; r++) sacc[nt][r] = 0.0f;

#pragma unroll
            for (int ks = 0; ks < 4; ks++) {
                const uint32_t kb = (uint32_t)(ks * 32);   // bytes
                uint32_t bf[8][2];
#pragma unroll
                for (int j = 0; j < 4; j++)
                    ldsm_x4(bf[2 * j][0], bf[2 * j][1], bf[2 * j + 1][0], bf[2 * j + 1][1],
                            kbase + ((j * 16 + brow) * VROW + bcol) * 2 + kb);
#pragma unroll
                for (int nt = 0; nt < 8; nt++)
                    mma_f16(sacc[nt], qf[ks], bf[nt]);
            }

            // ---- causal mask ----
            if (kt + 63 > q0 + wrow) {
#pragma unroll
                for (int nt = 0; nt < 8; nt++) {
                    const int c = kt + nt * 8 + 2 * tg;
                    if (c > r0g)     sacc[nt][0] = -1e30f;
                    if (c + 1 > r0g) sacc[nt][1] = -1e30f;
                    if (c > r1g)     sacc[nt][2] = -1e30f;
                    if (c + 1 > r1g) sacc[nt][3] = -1e30f;
                }
            }

            // ---- online softmax (fp32) ----
            float rmax0 = -1e30f, rmax1 = -1e30f;
#pragma unroll
            for (int nt = 0; nt < 8; nt++) {
                rmax0 = fmaxf(rmax0, fmaxf(sacc[nt][0], sacc[nt][1]));
                rmax1 = fmaxf(rmax1, fmaxf(sacc[nt][2], sacc[nt][3]));
            }
            rmax0 = fmaxf(rmax0, __shfl_xor_sync(0xffffffff, rmax0, 1));
            rmax0 = fmaxf(rmax0, __shfl_xor_sync(0xffffffff, rmax0, 2));
            rmax1 = fmaxf(rmax1, __shfl_xor_sync(0xffffffff, rmax1, 1));
            rmax1 = fmaxf(rmax1, __shfl_xor_sync(0xffffffff, rmax1, 2));

            const float mn0 = fmaxf(mrow[0], rmax0);
            const float mn1 = fmaxf(mrow[1], rmax1);
            const float corr0 = __expf(mrow[0] - mn0);
            const float corr1 = __expf(mrow[1] - mn1);
            mrow[0] = mn0; mrow[1] = mn1;

            float rs0 = 0.0f, rs1 = 0.0f;
            __half* p0row = Ps + (wrow + g) * VROW + 2 * tg;
            __half* p1row = Ps + (wrow + g + 8) * VROW + 2 * tg;
#pragma unroll
            for (int nt = 0; nt < 8; nt++) {
                const float e0 = __expf(sacc[nt][0] - mn0);
                const float e1 = __expf(sacc[nt][1] - mn0);
                const float e2 = __expf(sacc[nt][2] - mn1);
                const float e3 = __expf(sacc[nt][3] - mn1);
                rs0 += e0 + e1;
                rs1 += e2 + e3;
                *reinterpret_cast<__half2*>(p0row + nt * 8) = __floats2half2_rn(e0, e1);
                *reinterpret_cast<__half2*>(p1row + nt * 8) = __floats2half2_rn(e2, e3);
            }
            rs0 += __shfl_xor_sync(0xffffffff, rs0, 1);
            rs0 += __shfl_xor_sync(0xffffffff, rs0, 2);
            rs1 += __shfl_xor_sync(0xffffffff, rs1, 1);
            rs1 += __shfl_xor_sync(0xffffffff, rs1, 2);
            lrow[0] = lrow[0] * corr0 + rs0;
            lrow[1] = lrow[1] * corr1 + rs1;

#pragma unroll
            for (int nt = 0; nt < 8; nt++) {
                of[nt][0] *= corr0; of[nt][1] *= corr0;
                of[nt][2] *= corr1; of[nt][3] *= corr1;
            }
            __syncwarp();

            // ---- O += P * V; P via ldmatrix.x4, V via ldmatrix.x2.trans ----
#pragma unroll
            for (int ks = 0; ks < 4; ks++) {
                uint32_t a[4];
                ldsm_x4(a[0], a[1], a[2], a[3],
                        psbase + ((wrow + arow) * VROW + acol + ks * 16) * 2);
                const uint32_t lrowaddr = vbase + ((ks * 16 + (lane & 15)) * VROW) * 2;
#pragma unroll
                for (int nt = 0; nt < 8; nt++) {
                    uint32_t bf2[2];
                    ldsm_x2_trans(bf2[0], bf2[1], lrowaddr + nt * 16);
                    mma_f16(of[nt], a, bf2);
                }
            }
        }
        __syncthreads();
    }

    // ---- epilogue ----
    const float inv0 = 1.0f / lrow[0];
    const float inv1 = 1.0f / lrow[1];
    __half* o0 = O + (((size_t)b * SEQ + r0g) * NHEAD + h) * HDIM;
    __half* o1 = O + (((size_t)b * SEQ + r1g) * NHEAD + h) * HDIM;
#pragma unroll
    for (int nt = 0; nt < 8; nt++) {
        const int col = nt * 8 + 2 * tg;
        *reinterpret_cast<__half2*>(o0 + col) =
            __floats2half2_rn(of[nt][0] * inv0, of[nt][1] * inv0);
        *reinterpret_cast<__half2*>(o1 + col) =
            __floats2half2_rn(of[nt][2] * inv1, of[nt][3] * inv1);
    }
}

// ---------------------------------------------------------------------------
// kernel_launch
// ---------------------------------------------------------------------------
extern "C" void kernel_launch(void* const* d_in, const int* in_sizes, int n_in,
                              void* d_out, int out_size) {
    const float* x     = (const float*)d_in[0];
    const float* freqs = (const float*)d_in[1];
    const float* Wq    = (const float*)d_in[2];
    const float* Wk    = (const float*)d_in[3];
    const float* Wv    = (const float*)d_in[4];
    const float* Wo    = (const float*)d_in[5];
    float* out = (float*)d_out;

    __half *qh = nullptr, *kh = nullptr, *vh = nullptr;
    __half *attnh = nullptr, *xh = nullptr, *wh = nullptr;
    cudaGetSymbolAddress((void**)&qh,    g_qh);
    cudaGetSymbolAddress((void**)&kh,    g_kh);
    cudaGetSymbolAddress((void**)&vh,    g_vh);
    cudaGetSymbolAddress((void**)&attnh, g_attnh);
    cudaGetSymbolAddress((void**)&xh,    g_xh);
    cudaGetSymbolAddress((void**)&wh,    g_wh);

    cudaFuncSetAttribute(gemm_qkv,  cudaFuncAttributeMaxDynamicSharedMemorySize, GH_SMEM_BYTES);
    cudaFuncSetAttribute(gemm_proj, cudaFuncAttributeMaxDynamicSharedMemorySize, GH_SMEM_BYTES);
    cudaFuncSetAttribute(flash_attn_mma, cudaFuncAttributeMaxDynamicSharedMemorySize, HSMEM_BYTES);

    {
        const long long total = (long long)MROWS * CMODEL + 4LL * CMODEL * CMODEL;
        const int blocks = (int)(total / (256 * 8));
        to_half_all<<<blocks, 256>>>(x, Wq, Wk, Wv, Wo, xh, wh);
    }

    gemm_qkv<<<dim3(24, MROWS / 128), 256, GH_SMEM_BYTES>>>(xh, wh, qh, kh, vh, freqs);

    {
        dim3 agrid(SEQ / 128, NHEAD, BATCH);
        flash_attn_mma<<<agrid, 256, HSMEM_BYTES>>>(qh, kh, vh, attnh);
    }

    gemm_proj<<<dim3(CMODEL / 128, MROWS / 128), 256, GH_SMEM_BYTES>>>(attnh, wh, out);
}

// round 16
// speedup vs baseline: 2.4615x; 1.0606x over previous
#include <cuda_runtime.h>
#include <cuda_fp16.h>
#include <cstdint>
#include <math.h>

// Problem constants
#define BATCH 2
#define SEQ   2048
#define CMODEL 1024
#define NHEAD 16
#define HDIM  64
#define MROWS (BATCH * SEQ)   // 4096

// ---------------------------------------------------------------------------
// Scratch
// ---------------------------------------------------------------------------
__device__ __half g_qh[MROWS * CMODEL];
__device__ __half g_kh[MROWS * CMODEL];
__device__ __half g_vh[MROWS * CMODEL];
__device__ __half g_attnh[MROWS * CMODEL];
__device__ __half g_xh[MROWS * CMODEL];
__device__ __half g_wh[4 * CMODEL * CMODEL];

// ---------------------------------------------------------------------------
// Helpers
// ---------------------------------------------------------------------------
__device__ __forceinline__ uint32_t smem_u32(const void* p) {
    uint32_t a;
    asm("{ .reg .u64 t; cvta.to.shared.u64 t, %1; cvt.u32.u64 %0, t; }" : "=r"(a) : "l"(p));
    return a;
}
__device__ __forceinline__ void cp_async16(uint32_t s, const void* g) {
    asm volatile("cp.async.ca.shared.global [%0], [%1], 16;" :: "r"(s), "l"(g));
}
#define CP_COMMIT()  asm volatile("cp.async.commit_group;" ::: "memory")
#define CP_WAIT(N)   asm volatile("cp.async.wait_group %0;" :: "n"(N) : "memory")

__device__ __forceinline__ void mma_f16(float (&d)[4], const uint32_t (&a)[4],
                                        const uint32_t (&b)[2]) {
    asm volatile(
        "mma.sync.aligned.m16n8k16.row.col.f32.f16.f16.f32 "
        "{%0,%1,%2,%3}, {%4,%5,%6,%7}, {%8,%9}, {%0,%1,%2,%3};"
        : "+f"(d[0]), "+f"(d[1]), "+f"(d[2]), "+f"(d[3])
        : "r"(a[0]), "r"(a[1]), "r"(a[2]), "r"(a[3]), "r"(b[0]), "r"(b[1]));
}
__device__ __forceinline__ void ldsm_x4(uint32_t& r0, uint32_t& r1, uint32_t& r2,
                                        uint32_t& r3, uint32_t addr) {
    asm volatile("ldmatrix.sync.aligned.m8n8.x4.shared.b16 {%0,%1,%2,%3}, [%4];"
                 : "=r"(r0), "=r"(r1), "=r"(r2), "=r"(r3) : "r"(addr));
}
__device__ __forceinline__ void ldsm_x2_trans(uint32_t& r0, uint32_t& r1, uint32_t addr) {
    asm volatile("ldmatrix.sync.aligned.m8n8.x2.trans.shared.b16 {%0,%1}, [%2];"
                 : "=r"(r0), "=r"(r1) : "r"(addr));
}

// ---------------------------------------------------------------------------
// Fused prepass: fp32 -> fp16, one launch
// ---------------------------------------------------------------------------
__global__ void to_half_all(const float* __restrict__ x,
                            const float* __restrict__ wq,
                            const float* __restrict__ wk,
                            const float* __restrict__ wv,
                            const float* __restrict__ wo,
                            __half* __restrict__ xh,
                            __half* __restrict__ wh) {
    const long long nx = (long long)MROWS * CMODEL;
    const long long nw = (long long)CMODEL * CMODEL;
    long long i = (long long)(blockIdx.x * 256 + threadIdx.x) * 8;
    if (i >= nx + 4 * nw) return;

    const float* src;
    __half* dst;
    long long off;
    if (i < nx) {
        src = x; dst = xh; off = i;
    } else {
        long long j = i - nx;
        int s = (int)(j / nw);
        off = j - (long long)s * nw;
        src = (s == 0) ? wq : (s == 1) ? wk : (s == 2) ? wv : wo;
        dst = wh + (size_t)s * nw;
    }
    float4 v0 = *reinterpret_cast<const float4*>(src + off);
    float4 v1 = *reinterpret_cast<const float4*>(src + off + 4);
    __half2 h[4];
    h[0] = __floats2half2_rn(v0.x, v0.y);
    h[1] = __floats2half2_rn(v0.z, v0.w);
    h[2] = __floats2half2_rn(v1.x, v1.y);
    h[3] = __floats2half2_rn(v1.z, v1.w);
    *reinterpret_cast<uint2*>(dst + off)     = *reinterpret_cast<uint2*>(&h[0]);
    *reinterpret_cast<uint2*>(dst + off + 4) = *reinterpret_cast<uint2*>(&h[2]);
}

// ---------------------------------------------------------------------------
// FP16 GEMM: C = A * W^T. CTA 128x128, 128 threads = 4 warps in 2(M) x 2(N);
// warp tile 64x64 (4x8 mma tiles). 3-stage pipeline, ldmatrix, ONE barrier
// per K-tile, 2 CTAs/SM.
// ---------------------------------------------------------------------------
#define BK 32
#define KSTH 40
#define ATH (128 * KSTH)
#define WTH (128 * KSTH)
#define STAGEH (ATH + WTH)
#define GH_SMEM_BYTES (3 * STAGEH * 2)   // 61440

__device__ __forceinline__ void gemm_body_h(const __half* __restrict__ A,
                                            const __half* __restrict__ W,
                                            float* __restrict__ Cf,
                                            __half* __restrict__ Ch,
                                            const float* __restrict__ freqs,
                                            int m0, int n0, bool rope,
                                            __half* smem) {
    const int K = CMODEL, N = CMODEL;
    __half* As[3] = { smem, smem + STAGEH, smem + 2 * STAGEH };
    __half* Ws[3] = { smem + ATH, smem + STAGEH + ATH, smem + 2 * STAGEH + ATH };

    const int tid  = threadIdx.x;
    const int lane = tid & 31;
    const int wid  = tid >> 5;       // 0..3
    const int g    = lane >> 2;
    const int tg   = lane & 3;
    const int wm   = (wid & 1) * 64;
    const int wn   = (wid >> 1) * 64;

    // ldmatrix lane mappings
    const int arow = (lane & 7) + ((lane >> 3) & 1) * 8;   // A-type x4
    const int acol = (lane >> 4) * 8;
    const int brow = (lane & 7) + ((lane >> 4) & 1) * 8;   // B-type x4 (nt pair)
    const int bcol = ((lane >> 3) & 1) * 8;

    uint32_t aoff[4], boff[4];
#pragma unroll
    for (int mt = 0; mt < 4; mt++)
        aoff[mt] = ((wm + mt * 16 + arow) * KSTH + acol) * 2;
#pragma unroll
    for (int j = 0; j < 4; j++)
        boff[j] = (ATH + (wn + j * 16 + brow) * KSTH + bcol) * 2;

    float acc[4][8][4];
#pragma unroll
    for (int mt = 0; mt < 4; mt++)
#pragma unroll
        for (int nt = 0; nt < 8; nt++)
#pragma unroll
            for (int r = 0; r < 4; r++) acc[mt][nt][r] = 0.0f;

    const int ntiles = K / BK;   // 32

    // loaders (128 threads): A tile 512 chunks -> 4/thread; W same
    auto load_tile = [&](int kt, int stg) {
        const int ko = kt * BK;
#pragma unroll
        for (int i = 0; i < 4; i++) {
            const int f = tid + 128 * i;       // 0..511
            const int row = f >> 2;            // 0..127
            const int c8 = (f & 3) * 8;
            cp_async16(smem_u32(&As[stg][row * KSTH + c8]),
                       &A[(size_t)(m0 + row) * K + ko + c8]);
            cp_async16(smem_u32(&Ws[stg][row * KSTH + c8]),
                       &W[(size_t)(n0 + row) * K + ko + c8]);
        }
    };

    load_tile(0, 0);
    CP_COMMIT();
    load_tile(1, 1);
    CP_COMMIT();

    const uint32_t sbase = smem_u32(smem);

    for (int kt = 0; kt < ntiles; kt++) {
        if (kt + 1 < ntiles) { CP_WAIT(1); } else { CP_WAIT(0); }
        __syncthreads();
        if (kt + 2 < ntiles) {
            load_tile(kt + 2, (kt + 2) % 3);
            CP_COMMIT();
        }

        const uint32_t stg = sbase + (uint32_t)((kt % 3) * STAGEH * 2);
#pragma unroll
        for (int ks = 0; ks < 2; ks++) {
            const uint32_t kb = (uint32_t)(ks * 32);   // 16 halves = 32 bytes
            uint32_t a[4][4];
#pragma unroll
            for (int mt = 0; mt < 4; mt++)
                ldsm_x4(a[mt][0], a[mt][1], a[mt][2], a[mt][3], stg + aoff[mt] + kb);
            uint32_t b[8][2];
#pragma unroll
            for (int j = 0; j < 4; j++)
                ldsm_x4(b[2 * j][0], b[2 * j][1], b[2 * j + 1][0], b[2 * j + 1][1],
                        stg + boff[j] + kb);
#pragma unroll
            for (int mt = 0; mt < 4; mt++)
#pragma unroll
                for (int nt = 0; nt < 8; nt++)
                    mma_f16(acc[mt][nt], a[mt], b[nt]);
        }
        // no trailing barrier: next iteration's top barrier provides the
        // cross-warp ordering (3-stage ring, prefetch distance 2)
    }

    // epilogue
#pragma unroll
    for (int mt = 0; mt < 4; mt++) {
        const int row = m0 + wm + mt * 16 + g;
        const int t0 = row & (SEQ - 1);
        const int t1 = (row + 8) & (SEQ - 1);
#pragma unroll
        for (int nt = 0; nt < 8; nt++) {
            const int col = n0 + wn + nt * 8 + 2 * tg;
            float2 v0 = make_float2(acc[mt][nt][0], acc[mt][nt][1]);
            float2 v1 = make_float2(acc[mt][nt][2], acc[mt][nt][3]);
            if (rope) {
                const int fo = (col & 62);
                float cc0 = freqs[t0 * HDIM + fo], ss0 = freqs[t0 * HDIM + fo + 1];
                float cc1 = freqs[t1 * HDIM + fo], ss1 = freqs[t1 * HDIM + fo + 1];
                v0 = make_float2(v0.x * cc0 - v0.y * ss0, v0.x * ss0 + v0.y * cc0);
                v1 = make_float2(v1.x * cc1 - v1.y * ss1, v1.x * ss1 + v1.y * cc1);
            }
            if (Ch) {
                *reinterpret_cast<__half2*>(&Ch[(size_t)row * N + col]) =
                    __floats2half2_rn(v0.x, v0.y);
                *reinterpret_cast<__half2*>(&Ch[(size_t)(row + 8) * N + col]) =
                    __floats2half2_rn(v1.x, v1.y);
            } else {
                *reinterpret_cast<float2*>(&Cf[(size_t)row * N + col]) = v0;
                *reinterpret_cast<float2*>(&Cf[(size_t)(row + 8) * N + col]) = v1;
            }
        }
    }
}

__global__ __launch_bounds__(128, 2) void gemm_qkv(const __half* __restrict__ xh,
                                                   const __half* __restrict__ wh,
                                                   __half* __restrict__ q,
                                                   __half* __restrict__ k,
                                                   __half* __restrict__ v,
                                                   const float* __restrict__ freqs) {
    extern __shared__ __half smemh[];
    const int wsel = blockIdx.x >> 3;
    const int n0 = (blockIdx.x & 7) * 128;
    const int m0 = blockIdx.y * 128;
    const __half* W = wh + (size_t)wsel * CMODEL * CMODEL;
    __half* C = (wsel == 0) ? q : (wsel == 1) ? k : v;
    gemm_body_h(xh, W, nullptr, C, freqs, m0, n0, wsel < 2, smemh);
}

__global__ __launch_bounds__(128, 2) void gemm_proj(const __half* __restrict__ attnh,
                                                    const __half* __restrict__ wh,
                                                    float* __restrict__ C) {
    extern __shared__ __half smemh[];
    gemm_body_h(attnh, wh + (size_t)3 * CMODEL * CMODEL, C, nullptr, nullptr,
                blockIdx.y * 128, blockIdx.x * 128, false, smemh);
}

// ---------------------------------------------------------------------------
// FP16 flash-attention, causal. 3-stage pipeline, ldmatrix fragments,
// ONE barrier per tile, 2 CTAs/SM.
// ---------------------------------------------------------------------------
#define VROW 72
#define HTILE (64 * VROW)
#define HSMEM_BYTES (6 * HTILE * 2 + 128 * VROW * 2)   // 73728

__global__ __launch_bounds__(256, 2) void flash_attn_mma(const __half* __restrict__ Q,
                                                         const __half* __restrict__ K,
                                                         const __half* __restrict__ V,
                                                         __half* __restrict__ O) {
    extern __shared__ __half smh[];
    __half* Ps = smh + 6 * HTILE;        // [128][VROW]

    const int tid  = threadIdx.x;
    const int lane = tid & 31;
    const int wid  = tid >> 5;
    const int g    = lane >> 2;
    const int tg   = lane & 3;

    const int qb = (int)gridDim.x - 1 - (int)blockIdx.x;
    const int h  = blockIdx.y;
    const int b  = blockIdx.z;
    const int q0 = qb * 128;
    const int wrow = wid * 16;
    const int r0g = q0 + wrow + g;
    const int r1g = r0g + 8;

    const int arow = (lane & 7) + ((lane >> 3) & 1) * 8;
    const int acol = (lane >> 4) * 8;
    const int brow = (lane & 7) + ((lane >> 4) & 1) * 8;
    const int bcol = ((lane >> 3) & 1) * 8;

    const __half2 s2 = __half2half2(__float2half(0.125f));
    uint32_t qf[4][4];
    {
        const __half* q0p = Q + (((size_t)b * SEQ + r0g) * NHEAD + h) * HDIM;
        const __half* q1p = Q + (((size_t)b * SEQ + r1g) * NHEAD + h) * HDIM;
#pragma unroll
        for (int ks = 0; ks < 4; ks++) {
            const int kc = ks * 16 + 2 * tg;
            __half2 h0 = __hmul2(*reinterpret_cast<const __half2*>(q0p + kc), s2);
            __half2 h1 = __hmul2(*reinterpret_cast<const __half2*>(q1p + kc), s2);
            __half2 h2 = __hmul2(*reinterpret_cast<const __half2*>(q0p + kc + 8), s2);
            __half2 h3 = __hmul2(*reinterpret_cast<const __half2*>(q1p + kc + 8), s2);
            qf[ks][0] = *reinterpret_cast<uint32_t*>(&h0);
            qf[ks][1] = *reinterpret_cast<uint32_t*>(&h1);
            qf[ks][2] = *reinterpret_cast<uint32_t*>(&h2);
            qf[ks][3] = *reinterpret_cast<uint32_t*>(&h3);
        }
    }

    float of[8][4];
#pragma unroll
    for (int nt = 0; nt < 8; nt++)
#pragma unroll
        for (int r = 0; r < 4; r++) of[nt][r] = 0.0f;
    float mrow[2] = { -1e30f, -1e30f };
    float lrow[2] = { 0.0f, 0.0f };

    const int ntiles = (q0 + 128) / 64;

    const uint32_t ks0 = smem_u32(smh);
    const uint32_t stageB = 2 * HTILE * 2;
    const uint32_t psbase = smem_u32(Ps);

    auto prefetch = [&](int t, int s) {
        const int kt = t * 64;
#pragma unroll
        for (int i = 0; i < 2; i++) {
            const int f = tid + 256 * i;
            const int row = f >> 3;
            const int c8 = (f & 7) * 8;
            const size_t gsrc = (((size_t)b * SEQ + kt + row) * NHEAD + h) * HDIM + c8;
            const uint32_t soff = s * stageB + (row * VROW + c8) * 2;
            cp_async16(ks0 + soff, &K[gsrc]);
            cp_async16(ks0 + soff + HTILE * 2, &V[gsrc]);
        }
    };

    prefetch(0, 0);
    CP_COMMIT();
    prefetch(1, 1);
    CP_COMMIT();

    for (int t = 0; t < ntiles; t++) {
        const int kt = t * 64;
        if (t + 1 < ntiles) { CP_WAIT(1); } else { CP_WAIT(0); }
        __syncthreads();
        if (t + 2 < ntiles) {
            prefetch(t + 2, (t + 2) % 3);
            CP_COMMIT();
        }

        const bool skip = kt > q0 + wrow + 15;
        if (!skip) {
            const uint32_t kbase = ks0 + (t % 3) * stageB;
            const uint32_t vbase = kbase + HTILE * 2;

            float sacc[8][4];
#pragma unroll
            for (int nt = 0; nt < 8; nt++)
#pragma unroll
                for (int r = 0; r < 4; r++) sacc[nt][r] = 0.0f;

#pragma unroll
            for (int ks = 0; ks < 4; ks++) {
                const uint32_t kb = (uint32_t)(ks * 32);
                uint32_t bf[8][2];
#pragma unroll
                for (int j = 0; j < 4; j++)
                    ldsm_x4(bf[2 * j][0], bf[2 * j][1], bf[2 * j + 1][0], bf[2 * j + 1][1],
                            kbase + ((j * 16 + brow) * VROW + bcol) * 2 + kb);
#pragma unroll
                for (int nt = 0; nt < 8; nt++)
                    mma_f16(sacc[nt], qf[ks], bf[nt]);
            }

            if (kt + 63 > q0 + wrow) {
#pragma unroll
                for (int nt = 0; nt < 8; nt++) {
                    const int c = kt + nt * 8 + 2 * tg;
                    if (c > r0g)     sacc[nt][0] = -1e30f;
                    if (c + 1 > r0g) sacc[nt][1] = -1e30f;
                    if (c > r1g)     sacc[nt][2] = -1e30f;
                    if (c + 1 > r1g) sacc[nt][3] = -1e30f;
                }
            }

            float rmax0 = -1e30f, rmax1 = -1e30f;
#pragma unroll
            for (int nt = 0; nt < 8; nt++) {
                rmax0 = fmaxf(rmax0, fmaxf(sacc[nt][0], sacc[nt][1]));
                rmax1 = fmaxf(rmax1, fmaxf(sacc[nt][2], sacc[nt][3]));
            }
            rmax0 = fmaxf(rmax0, __shfl_xor_sync(0xffffffff, rmax0, 1));
            rmax0 = fmaxf(rmax0, __shfl_xor_sync(0xffffffff, rmax0, 2));
            rmax1 = fmaxf(rmax1, __shfl_xor_sync(0xffffffff, rmax1, 1));
            rmax1 = fmaxf(rmax1, __shfl_xor_sync(0xffffffff, rmax1, 2));

            const float mn0 = fmaxf(mrow[0], rmax0);
            const float mn1 = fmaxf(mrow[1], rmax1);
            const float corr0 = __expf(mrow[0] - mn0);
            const float corr1 = __expf(mrow[1] - mn1);
            mrow[0] = mn0; mrow[1] = mn1;

            float rs0 = 0.0f, rs1 = 0.0f;
            __half* p0row = Ps + (wrow + g) * VROW + 2 * tg;
            __half* p1row = Ps + (wrow + g + 8) * VROW + 2 * tg;
#pragma unroll
            for (int nt = 0; nt < 8; nt++) {
                const float e0 = __expf(sacc[nt][0] - mn0);
                const float e1 = __expf(sacc[nt][1] - mn0);
                const float e2 = __expf(sacc[nt][2] - mn1);
                const float e3 = __expf(sacc[nt][3] - mn1);
                rs0 += e0 + e1;
                rs1 += e2 + e3;
                *reinterpret_cast<__half2*>(p0row + nt * 8) = __floats2half2_rn(e0, e1);
                *reinterpret_cast<__half2*>(p1row + nt * 8) = __floats2half2_rn(e2, e3);
            }
            rs0 += __shfl_xor_sync(0xffffffff, rs0, 1);
            rs0 += __shfl_xor_sync(0xffffffff, rs0, 2);
            rs1 += __shfl_xor_sync(0xffffffff, rs1, 1);
            rs1 += __shfl_xor_sync(0xffffffff, rs1, 2);
            lrow[0] = lrow[0] * corr0 + rs0;
            lrow[1] = lrow[1] * corr1 + rs1;

#pragma unroll
            for (int nt = 0; nt < 8; nt++) {
                of[nt][0] *= corr0; of[nt][1] *= corr0;
                of[nt][2] *= corr1; of[nt][3] *= corr1;
            }
            __syncwarp();

#pragma unroll
            for (int ks = 0; ks < 4; ks++) {
                uint32_t a[4];
                ldsm_x4(a[0], a[1], a[2], a[3],
                        psbase + ((wrow + arow) * VROW + acol + ks * 16) * 2);
                const uint32_t lrowaddr = vbase + ((ks * 16 + (lane & 15)) * VROW) * 2;
#pragma unroll
                for (int nt = 0; nt < 8; nt++) {
                    uint32_t bf2[2];
                    ldsm_x2_trans(bf2[0], bf2[1], lrowaddr + nt * 16);
                    mma_f16(of[nt], a, bf2);
                }
            }
        }
        // no trailing barrier: Ps rows are per-warp private; K/V stage reuse
        // is protected by the next iteration's top barrier (3-stage ring)
    }

    const float inv0 = 1.0f / lrow[0];
    const float inv1 = 1.0f / lrow[1];
    __half* o0 = O + (((size_t)b * SEQ + r0g) * NHEAD + h) * HDIM;
    __half* o1 = O + (((size_t)b * SEQ + r1g) * NHEAD + h) * HDIM;
#pragma unroll
    for (int nt = 0; nt < 8; nt++) {
        const int col = nt * 8 + 2 * tg;
        *reinterpret_cast<__half2*>(o0 + col) =
            __floats2half2_rn(of[nt][0] * inv0, of[nt][1] * inv0);
        *reinterpret_cast<__half2*>(o1 + col) =
            __floats2half2_rn(of[nt][2] * inv1, of[nt][3] * inv1);
    }
}

// ---------------------------------------------------------------------------
// kernel_launch
// ---------------------------------------------------------------------------
extern "C" void kernel_launch(void* const* d_in, const int* in_sizes, int n_in,
                              void* d_out, int out_size) {
    const float* x     = (const float*)d_in[0];
    const float* freqs = (const float*)d_in[1];
    const float* Wq    = (const float*)d_in[2];
    const float* Wk    = (const float*)d_in[3];
    const float* Wv    = (const float*)d_in[4];
    const float* Wo    = (const float*)d_in[5];
    float* out = (float*)d_out;

    __half *qh = nullptr, *kh = nullptr, *vh = nullptr;
    __half *attnh = nullptr, *xh = nullptr, *wh = nullptr;
    cudaGetSymbolAddress((void**)&qh,    g_qh);
    cudaGetSymbolAddress((void**)&kh,    g_kh);
    cudaGetSymbolAddress((void**)&vh,    g_vh);
    cudaGetSymbolAddress((void**)&attnh, g_attnh);
    cudaGetSymbolAddress((void**)&xh,    g_xh);
    cudaGetSymbolAddress((void**)&wh,    g_wh);

    cudaFuncSetAttribute(gemm_qkv,  cudaFuncAttributeMaxDynamicSharedMemorySize, GH_SMEM_BYTES);
    cudaFuncSetAttribute(gemm_proj, cudaFuncAttributeMaxDynamicSharedMemorySize, GH_SMEM_BYTES);
    cudaFuncSetAttribute(flash_attn_mma, cudaFuncAttributeMaxDynamicSharedMemorySize, HSMEM_BYTES);

    {
        const long long total = (long long)MROWS * CMODEL + 4LL * CMODEL * CMODEL;
        const int blocks = (int)(total / (256 * 8));
        to_half_all<<<blocks, 256>>>(x, Wq, Wk, Wv, Wo, xh, wh);
    }

    gemm_qkv<<<dim3(24, MROWS / 128), 128, GH_SMEM_BYTES>>>(xh, wh, qh, kh, vh, freqs);

    {
        dim3 agrid(SEQ / 128, NHEAD, BATCH);
        flash_attn_mma<<<agrid, 256, HSMEM_BYTES>>>(qh, kh, vh, attnh);
    }

    gemm_proj<<<dim3(CMODEL / 128, MROWS / 128), 128, GH_SMEM_BYTES>>>(attnh, wh, out);
}